// round 1
// baseline (speedup 1.0000x reference)
#include <cuda_runtime.h>
#include <mma.h>
#include <math.h>

using namespace nvcuda;

#define B 4
#define L 2048
#define D 1024
#define H 16
#define DH 64
#define NROWS (B * L)   // 8192

// ---------------- scratch (no allocations allowed) ----------------
__device__ float g_q[(size_t)B * H * L * DH];   // [B][H][L][DH]
__device__ float g_k[(size_t)B * H * L * DH];
__device__ float g_v[(size_t)B * H * L * DH];
__device__ float g_z[(size_t)NROWS * D];        // [B*L][D]

// ---------------- helpers ----------------
__device__ __forceinline__ float4 tf32x4(float4 v) {
    v.x = wmma::__float_to_tf32(v.x);
    v.y = wmma::__float_to_tf32(v.y);
    v.z = wmma::__float_to_tf32(v.z);
    v.w = wmma::__float_to_tf32(v.w);
    return v;
}

// ---------------- GEMM (tf32 wmma), 128x128 block tile, BK=16 ----------------
#define BM 128
#define BN 128
#define BK 16
#define LDBS 132      // padded B-tile stride (floats), multiple of 4
#define STAGE_LD 132  // epilogue staging stride

#define GEMM_LOOP_SMEM ((BM * BK + BK * LDBS) * 4)       // 16640 B
#define GEMM_STAGE_SMEM (BM * STAGE_LD * 4)              // 67584 B

using FragAcc = wmma::fragment<wmma::accumulator, 16, 16, 8, float>;
using FragA   = wmma::fragment<wmma::matrix_a, 16, 16, 8, wmma::precision::tf32, wmma::row_major>;
using FragBR  = wmma::fragment<wmma::matrix_b, 16, 16, 8, wmma::precision::tf32, wmma::row_major>;
using FragBC  = wmma::fragment<wmma::matrix_b, 16, 16, 8, wmma::precision::tf32, wmma::col_major>;

// 256 threads = 8 warps; warp grid 2(M) x 4(N); each warp computes 64x32.
__device__ __forceinline__ void gemm_tile_loop(
    const float* __restrict__ A, const float* __restrict__ W,
    float* As, float* Bs, int row0, int col0, FragAcc acc[4][2])
{
    const int tid = threadIdx.x;
    const int warp = tid >> 5;
    const int wm = warp >> 2;   // 0..1
    const int wn = warp & 3;    // 0..3

    #pragma unroll
    for (int i = 0; i < 4; i++)
        #pragma unroll
        for (int j = 0; j < 2; j++)
            wmma::fill_fragment(acc[i][j], 0.0f);

    for (int k0 = 0; k0 < D; k0 += BK) {
        // A tile: 128x16 (512 float4, 2 per thread)
        {
            int idx = tid;
            #pragma unroll
            for (int rep = 0; rep < 2; rep++, idx += 256) {
                int r = idx >> 2;
                int c = (idx & 3) << 2;
                float4 v = *(const float4*)(A + (size_t)(row0 + r) * D + k0 + c);
                *(float4*)(As + r * BK + c) = tf32x4(v);
            }
        }
        // B tile: 16x128 (512 float4, 2 per thread)
        {
            int idx = tid;
            #pragma unroll
            for (int rep = 0; rep < 2; rep++, idx += 256) {
                int r = idx >> 5;
                int c = (idx & 31) << 2;
                float4 v = *(const float4*)(W + (size_t)(k0 + r) * D + col0 + c);
                *(float4*)(Bs + r * LDBS + c) = tf32x4(v);
            }
        }
        __syncthreads();

        #pragma unroll
        for (int kk = 0; kk < 2; kk++) {
            FragA a[4];
            FragBR b[2];
            #pragma unroll
            for (int i = 0; i < 4; i++)
                wmma::load_matrix_sync(a[i], As + (wm * 64 + i * 16) * BK + kk * 8, BK);
            #pragma unroll
            for (int j = 0; j < 2; j++)
                wmma::load_matrix_sync(b[j], Bs + (kk * 8) * LDBS + wn * 32 + j * 16, LDBS);
            #pragma unroll
            for (int i = 0; i < 4; i++)
                #pragma unroll
                for (int j = 0; j < 2; j++)
                    wmma::mma_sync(acc[i][j], a[i], b[j], acc[i][j]);
        }
        __syncthreads();
    }
}

// QKV projection: grid (D/BN, NROWS/BM, 3). Writes [B][H][L][DH].
__global__ void qkv_gemm(const float* __restrict__ x,
                         const float* __restrict__ Wq,
                         const float* __restrict__ Wk,
                         const float* __restrict__ Wv)
{
    extern __shared__ float smem[];
    float* As = smem;
    float* Bs = smem + BM * BK;

    const int row0 = blockIdx.y * BM;
    const int col0 = blockIdx.x * BN;
    const float* Wsel = (blockIdx.z == 0) ? Wq : (blockIdx.z == 1) ? Wk : Wv;
    float* Out = (blockIdx.z == 0) ? g_q : (blockIdx.z == 1) ? g_k : g_v;

    FragAcc acc[4][2];
    gemm_tile_loop(x, Wsel, As, Bs, row0, col0, acc);

    const int warp = threadIdx.x >> 5;
    const int wm = warp >> 2, wn = warp & 3;
    const int b = row0 / L;          // BM divides L, so b is constant per block
    const int l0 = row0 % L;

    #pragma unroll
    for (int i = 0; i < 4; i++) {
        #pragma unroll
        for (int j = 0; j < 2; j++) {
            int c = col0 + wn * 32 + j * 16;
            int h = c / DH;
            int dcol = c % DH;       // multiple of 16 -> aligned
            int m = l0 + wm * 64 + i * 16;
            float* dst = Out + (((size_t)(b * H + h) * L + m) * DH + dcol);
            wmma::store_matrix_sync(dst, acc[i][j], DH, wmma::mem_row_major);
        }
    }
}

// Output projection: z @ Wo, fused relu + residual. grid (D/BN, NROWS/BM).
__global__ void out_gemm(const float* __restrict__ Wo,
                         const float* __restrict__ x,
                         float* __restrict__ out)
{
    extern __shared__ float smem[];
    float* As = smem;
    float* Bs = smem + BM * BK;

    const int row0 = blockIdx.y * BM;
    const int col0 = blockIdx.x * BN;

    FragAcc acc[4][2];
    gemm_tile_loop(g_z, Wo, As, Bs, row0, col0, acc);

    // Stage accumulators into smem (loop ended with __syncthreads, safe to reuse)
    const int warp = threadIdx.x >> 5;
    const int wm = warp >> 2, wn = warp & 3;
    float* stage = smem;
    #pragma unroll
    for (int i = 0; i < 4; i++)
        #pragma unroll
        for (int j = 0; j < 2; j++)
            wmma::store_matrix_sync(stage + (wm * 64 + i * 16) * STAGE_LD + wn * 32 + j * 16,
                                    acc[i][j], STAGE_LD, wmma::mem_row_major);
    __syncthreads();

    for (int idx = threadIdx.x; idx < BM * BN / 4; idx += 256) {
        int r = idx >> 5;            // /32
        int c = (idx & 31) << 2;
        float4 a = *(float4*)(stage + r * STAGE_LD + c);
        float4 xr = *(const float4*)(x + (size_t)(row0 + r) * D + col0 + c);
        a.x = fmaxf(a.x, 0.f) + xr.x;
        a.y = fmaxf(a.y, 0.f) + xr.y;
        a.z = fmaxf(a.z, 0.f) + xr.z;
        a.w = fmaxf(a.w, 0.f) + xr.w;
        *(float4*)(out + (size_t)(row0 + r) * D + col0 + c) = a;
    }
}

// ---------------- causal flash attention (tf32 wmma) ----------------
#define FM 64
#define FN 64
#define FLD 72  // padded row stride
#define FLASH_SMEM ((5 * FM * FLD + 3 * FM) * 4)  // 92928 B

// grid: (L/FM, H, B), 128 threads (4 warps), warp w owns query rows [16w,16w+16)
__global__ void flash_attn()
{
    extern __shared__ float fs[];
    float* Qs = fs;
    float* Ks = Qs + FM * FLD;
    float* Vs = Ks + FM * FLD;
    float* Ps = Vs + FM * FLD;
    float* Os = Ps + FM * FLD;
    float* mi  = Os + FM * FLD;
    float* li  = mi + FM;
    float* alp = li + FM;

    const int mt = blockIdx.x, h = blockIdx.y, b = blockIdx.z;
    const int tid = threadIdx.x;
    const int warp = tid >> 5;
    const int lane = tid & 31;
    const int m0 = mt * FM;

    const size_t head_off = ((size_t)(b * H + h) * L) * DH;
    const float* Qg = g_q + head_off;
    const float* Kg = g_k + head_off;
    const float* Vg = g_v + head_off;

    // load Q tile (tf32-rounded)
    for (int idx = tid; idx < FM * DH / 4; idx += 128) {
        int r = idx >> 4;
        int c = (idx & 15) << 2;
        float4 v = *(const float4*)(Qg + (size_t)(m0 + r) * DH + c);
        *(float4*)(Qs + r * FLD + c) = tf32x4(v);
    }
    for (int idx = tid; idx < FM * DH; idx += 128) {
        int r = idx >> 6, c = idx & 63;
        Os[r * FLD + c] = 0.f;
    }
    if (tid < FM) { mi[tid] = -1e30f; li[tid] = 0.f; }
    __syncthreads();

    const float scale = 0.125f;  // 1/sqrt(64)

    for (int nt = 0; nt <= mt; nt++) {
        const int n0 = nt * FM;
        // load K, V tiles
        for (int idx = tid; idx < FM * DH / 4; idx += 128) {
            int r = idx >> 4;
            int c = (idx & 15) << 2;
            float4 kv = *(const float4*)(Kg + (size_t)(n0 + r) * DH + c);
            *(float4*)(Ks + r * FLD + c) = tf32x4(kv);
            float4 vv = *(const float4*)(Vg + (size_t)(n0 + r) * DH + c);
            *(float4*)(Vs + r * FLD + c) = tf32x4(vv);
        }
        __syncthreads();

        // S = Q * K^T for this warp's 16-row strip
        FragAcc sacc[4];
        #pragma unroll
        for (int j = 0; j < 4; j++) wmma::fill_fragment(sacc[j], 0.f);
        #pragma unroll
        for (int kk = 0; kk < 8; kk++) {
            FragA af;
            wmma::load_matrix_sync(af, Qs + (warp * 16) * FLD + kk * 8, FLD);
            #pragma unroll
            for (int j = 0; j < 4; j++) {
                FragBC bf;
                wmma::load_matrix_sync(bf, Ks + (j * 16) * FLD + kk * 8, FLD);
                wmma::mma_sync(sacc[j], af, bf, sacc[j]);
            }
        }
        #pragma unroll
        for (int j = 0; j < 4; j++) {
            #pragma unroll
            for (int t = 0; t < sacc[j].num_elements; t++) sacc[j].x[t] *= scale;
            wmma::store_matrix_sync(Ps + (warp * 16) * FLD + j * 16, sacc[j], FLD, wmma::mem_row_major);
        }
        __syncwarp();

        // online softmax (warp-local rows; lanes 0..15 each own one row)
        if (lane < 16) {
            int r = warp * 16 + lane;
            float* Sr = Ps + r * FLD;
            if (nt == mt) {
                for (int j = r + 1; j < FN; j++) Sr[j] = -1e30f;
            }
            float mold = mi[r];
            float mx = mold;
            #pragma unroll 8
            for (int j = 0; j < FN; j++) mx = fmaxf(mx, Sr[j]);
            float a = __expf(mold - mx);
            float s = 0.f;
            #pragma unroll 8
            for (int j = 0; j < FN; j++) {
                float p = __expf(Sr[j] - mx);
                Sr[j] = wmma::__float_to_tf32(p);
                s += p;
            }
            li[r] = li[r] * a + s;
            mi[r] = mx;
            alp[r] = a;
        }
        __syncwarp();

        // rescale O rows (warp-local)
        for (int idx = lane; idx < 16 * DH; idx += 32) {
            int rr = idx >> 6, cc = idx & 63;
            int r = warp * 16 + rr;
            Os[r * FLD + cc] *= alp[r];
        }
        __syncwarp();

        // O += P * V
        FragAcc oacc[4];
        #pragma unroll
        for (int j = 0; j < 4; j++) wmma::fill_fragment(oacc[j], 0.f);
        #pragma unroll
        for (int kk = 0; kk < 8; kk++) {
            FragA af;
            wmma::load_matrix_sync(af, Ps + (warp * 16) * FLD + kk * 8, FLD);
            #pragma unroll
            for (int j = 0; j < 4; j++) {
                FragBR bf;
                wmma::load_matrix_sync(bf, Vs + (kk * 8) * FLD + j * 16, FLD);
                wmma::mma_sync(oacc[j], af, bf, oacc[j]);
            }
        }
        // stash PV into own Ps rows, then accumulate into Os (warp-local, no hazard)
        #pragma unroll
        for (int j = 0; j < 4; j++)
            wmma::store_matrix_sync(Ps + (warp * 16) * FLD + j * 16, oacc[j], FLD, wmma::mem_row_major);
        __syncwarp();
        for (int idx = lane; idx < 16 * DH; idx += 32) {
            int rr = idx >> 6, cc = idx & 63;
            int r = warp * 16 + rr;
            Os[r * FLD + cc] += Ps[r * FLD + cc];
        }
        __syncthreads();  // protect Ks/Vs before next iteration's load
    }

    // epilogue: normalize and write z in [B*L][D] layout
    for (int idx = tid; idx < FM * DH; idx += 128) {
        int r = idx >> 6, c = idx & 63;
        float v = Os[r * FLD + c] / li[r];
        g_z[((size_t)(b * L + m0 + r)) * D + h * DH + c] = v;
    }
}

// ---------------- layernorm (in-place on out) ----------------
__global__ void layernorm_kernel(float* __restrict__ out,
                                 const float* __restrict__ gamma,
                                 const float* __restrict__ beta)
{
    __shared__ float row[D];
    __shared__ float red[8];
    const int r = blockIdx.x;
    const int tid = threadIdx.x;
    float* o = out + (size_t)r * D;

    float s = 0.f;
    for (int c = tid; c < D; c += 256) {
        float v = o[c];
        row[c] = v;
        s += v;
    }
    // block reduce (sum)
    {
        for (int off = 16; off; off >>= 1) s += __shfl_xor_sync(0xffffffffu, s, off);
        if ((tid & 31) == 0) red[tid >> 5] = s;
        __syncthreads();
        if (tid < 32) {
            float v = (tid < 8) ? red[tid] : 0.f;
            for (int off = 4; off; off >>= 1) v += __shfl_xor_sync(0xffffffffu, v, off);
            if (tid == 0) red[0] = v;
        }
        __syncthreads();
    }
    const float mu = red[0] * (1.0f / D);
    __syncthreads();

    float vs = 0.f;
    for (int c = tid; c < D; c += 256) {
        float d = row[c] - mu;
        vs += d * d;
    }
    {
        for (int off = 16; off; off >>= 1) vs += __shfl_xor_sync(0xffffffffu, vs, off);
        if ((tid & 31) == 0) red[tid >> 5] = vs;
        __syncthreads();
        if (tid < 32) {
            float v = (tid < 8) ? red[tid] : 0.f;
            for (int off = 4; off; off >>= 1) v += __shfl_xor_sync(0xffffffffu, v, off);
            if (tid == 0) red[0] = v;
        }
        __syncthreads();
    }
    const float inv = rsqrtf(red[0] * (1.0f / D) + 1e-12f);

    for (int c = tid; c < D; c += 256)
        o[c] = (row[c] - mu) * inv * gamma[c] + beta[c];
}

// ---------------- launch ----------------
extern "C" void kernel_launch(void* const* d_in, const int* in_sizes, int n_in,
                              void* d_out, int out_size)
{
    const float* x     = (const float*)d_in[0];
    const float* Wq    = (const float*)d_in[1];
    const float* Wk    = (const float*)d_in[2];
    const float* Wv    = (const float*)d_in[3];
    const float* Wo    = (const float*)d_in[4];
    const float* gamma = (const float*)d_in[5];
    const float* beta  = (const float*)d_in[6];
    float* out = (float*)d_out;

    cudaFuncSetAttribute(out_gemm, cudaFuncAttributeMaxDynamicSharedMemorySize, GEMM_STAGE_SMEM);
    cudaFuncSetAttribute(flash_attn, cudaFuncAttributeMaxDynamicSharedMemorySize, FLASH_SMEM);

    dim3 g1(D / BN, NROWS / BM, 3);
    qkv_gemm<<<g1, 256, GEMM_LOOP_SMEM>>>(x, Wq, Wk, Wv);

    dim3 g2(L / FM, H, B);
    flash_attn<<<g2, 128, FLASH_SMEM>>>();

    dim3 g3(D / BN, NROWS / BM);
    out_gemm<<<g3, 256, GEMM_STAGE_SMEM>>>(Wo, x, out);

    layernorm_kernel<<<NROWS, 256>>>(out, gamma, beta);
}

// round 2
// speedup vs baseline: 2.3679x; 2.3679x over previous
#include <cuda_runtime.h>
#include <cuda_bf16.h>
#include <mma.h>
#include <math.h>

using namespace nvcuda;

#define B 4
#define L 2048
#define D 1024
#define H 16
#define DH 64
#define NROWS (B * L)   // 8192

typedef __nv_bfloat16 bf16;

// ---------------- scratch (no allocations allowed) ----------------
__device__ bf16 g_q[(size_t)B * H * L * DH];   // [B][H][L][DH] bf16
__device__ bf16 g_k[(size_t)B * H * L * DH];
__device__ bf16 g_v[(size_t)B * H * L * DH];
__device__ bf16 g_z[(size_t)NROWS * D];        // [B*L][D] bf16

// ---------------- helpers ----------------
__device__ __forceinline__ uint2 pack4bf(float4 v) {
    __nv_bfloat162 lo = __float22bfloat162_rn(make_float2(v.x, v.y));
    __nv_bfloat162 hi = __float22bfloat162_rn(make_float2(v.z, v.w));
    uint2 u;
    u.x = *(unsigned int*)&lo;
    u.y = *(unsigned int*)&hi;
    return u;
}

// ---------------- GEMM (bf16 wmma), 128x128 tile, BK=32, double-buffered ----------------
#define BM 128
#define BN 128
#define BKb 32
#define ALD 40    // A smem stride (bf16 elems)
#define BLD 136   // B smem stride (bf16 elems)
#define STAGE_LD 132

#define GEMM_SMEM_BYTES 67584   // max(2*(128*40+32*136)*2 = 37888, 128*132*4 = 67584)

using FA  = wmma::fragment<wmma::matrix_a, 16, 16, 16, bf16, wmma::row_major>;
using FBr = wmma::fragment<wmma::matrix_b, 16, 16, 16, bf16, wmma::row_major>;
using FBc = wmma::fragment<wmma::matrix_b, 16, 16, 16, bf16, wmma::col_major>;
using FC  = wmma::fragment<wmma::accumulator, 16, 16, 16, float>;

// 256 threads = 8 warps: warp grid 2(M) x 4(N), each warp 64x32.
// A is fp32 (A_BF16=false) or bf16 (A_BF16=true); W always fp32.
template<bool A_BF16>
__device__ __forceinline__ void gemm_loop(
    const void* __restrict__ Av, const float* __restrict__ W,
    bf16* As, bf16* Bs, int row0, int col0, FC acc[4][2])
{
    const int tid = threadIdx.x;
    const int warp = tid >> 5;
    const int wm = warp >> 2;
    const int wn = warp & 3;

    #pragma unroll
    for (int i = 0; i < 4; i++)
        #pragma unroll
        for (int j = 0; j < 2; j++)
            wmma::fill_fragment(acc[i][j], 0.0f);

    const int NT = D / BKb;  // 32
    const size_t abuf = (size_t)BM * ALD;
    const size_t bbuf = (size_t)BKb * BLD;

    // prologue: tile 0 into buffer 0
    {
        if (A_BF16) {
            const bf16* A = (const bf16*)Av;
            #pragma unroll
            for (int rep = 0; rep < 2; rep++) {
                int idx = tid + rep * 256;
                int r = idx >> 2, c = (idx & 3) << 3;
                uint4 u = *(const uint4*)(A + (size_t)(row0 + r) * D + c);
                *(uint4*)(As + r * ALD + c) = u;
            }
        } else {
            const float* A = (const float*)Av;
            #pragma unroll
            for (int rep = 0; rep < 4; rep++) {
                int idx = tid + rep * 256;
                int r = idx >> 3, c = (idx & 7) << 2;
                float4 v = *(const float4*)(A + (size_t)(row0 + r) * D + c);
                *(uint2*)(As + r * ALD + c) = pack4bf(v);
            }
        }
        #pragma unroll
        for (int rep = 0; rep < 4; rep++) {
            int idx = tid + rep * 256;
            int r = idx >> 5, c = (idx & 31) << 2;
            float4 v = *(const float4*)(W + (size_t)r * D + col0 + c);
            *(uint2*)(Bs + r * BLD + c) = pack4bf(v);
        }
    }
    __syncthreads();

    for (int t = 0; t < NT; t++) {
        bf16* Ac = As + (t & 1) * abuf;
        bf16* Bc = Bs + (t & 1) * bbuf;
        bf16* An = As + ((t + 1) & 1) * abuf;
        bf16* Bn = Bs + ((t + 1) & 1) * bbuf;
        const int k0n = (t + 1) * BKb;
        const bool more = (t + 1 < NT);

        // prefetch next tile to registers
        float4 rb[4];
        float4 rafp[4];
        uint4  rabf[2];
        if (more) {
            if (A_BF16) {
                const bf16* A = (const bf16*)Av;
                #pragma unroll
                for (int rep = 0; rep < 2; rep++) {
                    int idx = tid + rep * 256;
                    int r = idx >> 2, c = (idx & 3) << 3;
                    rabf[rep] = *(const uint4*)(A + (size_t)(row0 + r) * D + k0n + c);
                }
            } else {
                const float* A = (const float*)Av;
                #pragma unroll
                for (int rep = 0; rep < 4; rep++) {
                    int idx = tid + rep * 256;
                    int r = idx >> 3, c = (idx & 7) << 2;
                    rafp[rep] = *(const float4*)(A + (size_t)(row0 + r) * D + k0n + c);
                }
            }
            #pragma unroll
            for (int rep = 0; rep < 4; rep++) {
                int idx = tid + rep * 256;
                int r = idx >> 5, c = (idx & 31) << 2;
                rb[rep] = *(const float4*)(W + (size_t)(k0n + r) * D + col0 + c);
            }
        }

        // compute current tile
        #pragma unroll
        for (int kk = 0; kk < 2; kk++) {
            FA a[4];
            FBr b[2];
            #pragma unroll
            for (int i = 0; i < 4; i++)
                wmma::load_matrix_sync(a[i], Ac + (wm * 64 + i * 16) * ALD + kk * 16, ALD);
            #pragma unroll
            for (int j = 0; j < 2; j++)
                wmma::load_matrix_sync(b[j], Bc + (kk * 16) * BLD + wn * 32 + j * 16, BLD);
            #pragma unroll
            for (int i = 0; i < 4; i++)
                #pragma unroll
                for (int j = 0; j < 2; j++)
                    wmma::mma_sync(acc[i][j], a[i], b[j], acc[i][j]);
        }

        // store prefetched tile to next buffer
        if (more) {
            if (A_BF16) {
                #pragma unroll
                for (int rep = 0; rep < 2; rep++) {
                    int idx = tid + rep * 256;
                    int r = idx >> 2, c = (idx & 3) << 3;
                    *(uint4*)(An + r * ALD + c) = rabf[rep];
                }
            } else {
                #pragma unroll
                for (int rep = 0; rep < 4; rep++) {
                    int idx = tid + rep * 256;
                    int r = idx >> 3, c = (idx & 7) << 2;
                    *(uint2*)(An + r * ALD + c) = pack4bf(rafp[rep]);
                }
            }
            #pragma unroll
            for (int rep = 0; rep < 4; rep++) {
                int idx = tid + rep * 256;
                int r = idx >> 5, c = (idx & 31) << 2;
                *(uint2*)(Bn + r * BLD + c) = pack4bf(rb[rep]);
            }
        }
        __syncthreads();
    }
}

// QKV projection: grid (D/BN, NROWS/BM, 3). Output bf16 [B][H][L][DH].
__global__ void qkv_gemm(const float* __restrict__ x,
                         const float* __restrict__ Wq,
                         const float* __restrict__ Wk,
                         const float* __restrict__ Wv)
{
    extern __shared__ char smem[];
    bf16* As = (bf16*)smem;
    bf16* Bs = As + 2 * BM * ALD;

    const int row0 = blockIdx.y * BM;
    const int col0 = blockIdx.x * BN;
    const float* Wsel = (blockIdx.z == 0) ? Wq : (blockIdx.z == 1) ? Wk : Wv;
    bf16* Out = (blockIdx.z == 0) ? g_q : (blockIdx.z == 1) ? g_k : g_v;

    FC acc[4][2];
    gemm_loop<false>(x, Wsel, As, Bs, row0, col0, acc);

    // stage fp32, then write bf16 in head layout
    float* stage = (float*)smem;
    const int warp = threadIdx.x >> 5;
    const int wm = warp >> 2, wn = warp & 3;
    #pragma unroll
    for (int i = 0; i < 4; i++)
        #pragma unroll
        for (int j = 0; j < 2; j++)
            wmma::store_matrix_sync(stage + (wm * 64 + i * 16) * STAGE_LD + wn * 32 + j * 16,
                                    acc[i][j], STAGE_LD, wmma::mem_row_major);
    __syncthreads();

    const int b = row0 / L;
    const int l0 = row0 % L;
    for (int idx = threadIdx.x; idx < BM * BN / 4; idx += 256) {
        int r = idx >> 5;
        int c = (idx & 31) << 2;
        float4 v = *(float4*)(stage + r * STAGE_LD + c);
        int gc = col0 + c;
        int h = gc >> 6;
        int d = gc & 63;
        bf16* dst = Out + (((size_t)(b * H + h) * L + l0 + r) * DH + d);
        *(uint2*)dst = pack4bf(v);
    }
}

// Output projection: z @ Wo, fused relu + residual. grid (D/BN, NROWS/BM).
__global__ void out_gemm(const float* __restrict__ Wo,
                         const float* __restrict__ x,
                         float* __restrict__ out)
{
    extern __shared__ char smem[];
    bf16* As = (bf16*)smem;
    bf16* Bs = As + 2 * BM * ALD;

    const int row0 = blockIdx.y * BM;
    const int col0 = blockIdx.x * BN;

    FC acc[4][2];
    gemm_loop<true>(g_z, Wo, As, Bs, row0, col0, acc);

    float* stage = (float*)smem;
    const int warp = threadIdx.x >> 5;
    const int wm = warp >> 2, wn = warp & 3;
    #pragma unroll
    for (int i = 0; i < 4; i++)
        #pragma unroll
        for (int j = 0; j < 2; j++)
            wmma::store_matrix_sync(stage + (wm * 64 + i * 16) * STAGE_LD + wn * 32 + j * 16,
                                    acc[i][j], STAGE_LD, wmma::mem_row_major);
    __syncthreads();

    for (int idx = threadIdx.x; idx < BM * BN / 4; idx += 256) {
        int r = idx >> 5;
        int c = (idx & 31) << 2;
        float4 a = *(float4*)(stage + r * STAGE_LD + c);
        float4 xr = *(const float4*)(x + (size_t)(row0 + r) * D + col0 + c);
        a.x = fmaxf(a.x, 0.f) + xr.x;
        a.y = fmaxf(a.y, 0.f) + xr.y;
        a.z = fmaxf(a.z, 0.f) + xr.z;
        a.w = fmaxf(a.w, 0.f) + xr.w;
        *(float4*)(out + (size_t)(row0 + r) * D + col0 + c) = a;
    }
}

// ---------------- causal flash attention (bf16 wmma, O in registers) ----------------
#define AFM 128   // query rows per block
#define AFN 64    // keys per iteration
#define QLD 72
#define KLD 72
#define VLD 72
#define SLD 68    // fp32 staging stride
#define PLD 72
// smem: Q(128*72) + K(64*72) + V(64*72) bf16 = 36864B; S 128*68 f32 = 34816B; P 128*72 bf16 = 18432B
#define FLASH_SMEM (36864 + 34816 + 18432)   // 90112

// grid (L/AFM, H, B), 256 threads = 8 warps; warp w owns query rows [16w, 16w+16).
// Lane layout for softmax/O: row = lane&15, half = lane>>4 covers cols half*32..+32.
__global__ void flash_attn()
{
    extern __shared__ char fsm[];
    bf16* Qs = (bf16*)fsm;
    bf16* Ks = Qs + AFM * QLD;
    bf16* Vs = Ks + AFN * KLD;
    float* Sp = (float*)(Vs + AFN * VLD);
    bf16* Pb = (bf16*)(Sp + AFM * SLD);

    const int mt = blockIdx.x, h = blockIdx.y, b = blockIdx.z;
    const int tid = threadIdx.x;
    const int warp = tid >> 5;
    const int lane = tid & 31;
    const int m0 = mt * AFM;

    const size_t head_off = ((size_t)(b * H + h) * L) * DH;
    const bf16* Qg = g_q + head_off;
    const bf16* Kg = g_k + head_off;
    const bf16* Vg = g_v + head_off;

    // load Q tile (128x64 bf16): 1024 uint4, 4 per thread
    #pragma unroll
    for (int rep = 0; rep < 4; rep++) {
        int idx = tid + rep * 256;
        int r = idx >> 3, c = (idx & 7) << 3;
        *(uint4*)(Qs + r * QLD + c) = *(const uint4*)(Qg + (size_t)(m0 + r) * DH + c);
    }

    const int r = lane & 15;
    const int half = lane >> 4;
    const int rg = m0 + warp * 16 + r;   // global query row for this lane
    float o[32];
    #pragma unroll
    for (int j = 0; j < 32; j++) o[j] = 0.f;
    float mrow = -1e30f, lrow = 0.f;

    const int ntmax = (m0 + AFM - 1) / AFN;   // inclusive

    for (int nt = 0; nt <= ntmax; nt++) {
        const int n0 = nt * AFN;
        // load K,V tiles (64x64 bf16 each): 512 uint4 each, interleave threads
        #pragma unroll
        for (int rep = 0; rep < 2; rep++) {
            int idx = tid + rep * 256;
            int rr = idx >> 3, cc = (idx & 7) << 3;
            *(uint4*)(Ks + rr * KLD + cc) = *(const uint4*)(Kg + (size_t)(n0 + rr) * DH + cc);
            *(uint4*)(Vs + rr * VLD + cc) = *(const uint4*)(Vg + (size_t)(n0 + rr) * DH + cc);
        }
        __syncthreads();

        // S = Q K^T for warp's 16-row strip
        FC sacc[4];
        #pragma unroll
        for (int j = 0; j < 4; j++) wmma::fill_fragment(sacc[j], 0.f);
        #pragma unroll
        for (int kk = 0; kk < 4; kk++) {
            FA af;
            wmma::load_matrix_sync(af, Qs + (warp * 16) * QLD + kk * 16, QLD);
            #pragma unroll
            for (int j = 0; j < 4; j++) {
                FBc bf;
                wmma::load_matrix_sync(bf, Ks + (j * 16) * KLD + kk * 16, KLD);
                wmma::mma_sync(sacc[j], af, bf, sacc[j]);
            }
        }
        #pragma unroll
        for (int j = 0; j < 4; j++) {
            #pragma unroll
            for (int t = 0; t < sacc[j].num_elements; t++) sacc[j].x[t] *= 0.125f;
            wmma::store_matrix_sync(Sp + (warp * 16) * SLD + j * 16, sacc[j], SLD, wmma::mem_row_major);
        }
        __syncwarp();

        // online softmax: each lane owns (row r, cols half*32..+32)
        const float* Sr = Sp + (warp * 16 + r) * SLD + half * 32;
        const int cbase = n0 + half * 32;
        float mx = mrow;
        #pragma unroll
        for (int j = 0; j < 32; j++) {
            float s = Sr[j];
            s = (cbase + j <= rg) ? s : -1e30f;
            mx = fmaxf(mx, s);
        }
        mx = fmaxf(mx, __shfl_xor_sync(0xffffffffu, mx, 16));
        const float alpha = __expf(mrow - mx);

        bf16* Pr = Pb + (warp * 16 + r) * PLD + half * 32;
        float ssum = 0.f;
        #pragma unroll
        for (int j = 0; j < 32; j++) {
            float s = Sr[j];
            s = (cbase + j <= rg) ? s : -1e30f;
            float p = __expf(s - mx);
            ssum += p;
            Pr[j] = __float2bfloat16(p);
        }
        ssum += __shfl_xor_sync(0xffffffffu, ssum, 16);
        lrow = lrow * alpha + ssum;
        mrow = mx;
        #pragma unroll
        for (int j = 0; j < 32; j++) o[j] *= alpha;
        __syncwarp();

        // O += P V
        FC oacc[4];
        #pragma unroll
        for (int j = 0; j < 4; j++) wmma::fill_fragment(oacc[j], 0.f);
        #pragma unroll
        for (int kk = 0; kk < 4; kk++) {
            FA af;
            wmma::load_matrix_sync(af, Pb + (warp * 16) * PLD + kk * 16, PLD);
            #pragma unroll
            for (int j = 0; j < 4; j++) {
                FBr bfr;
                wmma::load_matrix_sync(bfr, Vs + (kk * 16) * VLD + j * 16, VLD);
                wmma::mma_sync(oacc[j], af, bfr, oacc[j]);
            }
        }
        #pragma unroll
        for (int j = 0; j < 4; j++)
            wmma::store_matrix_sync(Sp + (warp * 16) * SLD + j * 16, oacc[j], SLD, wmma::mem_row_major);
        __syncwarp();

        const float* Or = Sp + (warp * 16 + r) * SLD + half * 32;
        #pragma unroll
        for (int j = 0; j < 32; j++) o[j] += Or[j];

        __syncthreads();   // protect K/V/S before next iteration
    }

    // epilogue: normalize, write z bf16 in [B*L][D] layout
    const float rl = 1.0f / lrow;
    bf16* zr = g_z + ((size_t)(b * L + m0 + warp * 16 + r)) * D + h * DH + half * 32;
    #pragma unroll
    for (int j = 0; j < 32; j += 2) {
        __nv_bfloat162 h2 = __float22bfloat162_rn(make_float2(o[j] * rl, o[j + 1] * rl));
        *(__nv_bfloat162*)(zr + j) = h2;
    }
}

// ---------------- layernorm (in-place on out) ----------------
__global__ void layernorm_kernel(float* __restrict__ out,
                                 const float* __restrict__ gamma,
                                 const float* __restrict__ beta)
{
    __shared__ float row[D];
    __shared__ float red[8];
    const int r = blockIdx.x;
    const int tid = threadIdx.x;
    float* o = out + (size_t)r * D;

    float s = 0.f;
    for (int c = tid; c < D; c += 256) {
        float v = o[c];
        row[c] = v;
        s += v;
    }
    {
        for (int off = 16; off; off >>= 1) s += __shfl_xor_sync(0xffffffffu, s, off);
        if ((tid & 31) == 0) red[tid >> 5] = s;
        __syncthreads();
        if (tid < 32) {
            float v = (tid < 8) ? red[tid] : 0.f;
            for (int off = 4; off; off >>= 1) v += __shfl_xor_sync(0xffffffffu, v, off);
            if (tid == 0) red[0] = v;
        }
        __syncthreads();
    }
    const float mu = red[0] * (1.0f / D);
    __syncthreads();

    float vs = 0.f;
    for (int c = tid; c < D; c += 256) {
        float d = row[c] - mu;
        vs += d * d;
    }
    {
        for (int off = 16; off; off >>= 1) vs += __shfl_xor_sync(0xffffffffu, vs, off);
        if ((tid & 31) == 0) red[tid >> 5] = vs;
        __syncthreads();
        if (tid < 32) {
            float v = (tid < 8) ? red[tid] : 0.f;
            for (int off = 4; off; off >>= 1) v += __shfl_xor_sync(0xffffffffu, v, off);
            if (tid == 0) red[0] = v;
        }
        __syncthreads();
    }
    const float inv = rsqrtf(red[0] * (1.0f / D) + 1e-12f);

    for (int c = tid; c < D; c += 256)
        o[c] = (row[c] - mu) * inv * gamma[c] + beta[c];
}

// ---------------- launch ----------------
extern "C" void kernel_launch(void* const* d_in, const int* in_sizes, int n_in,
                              void* d_out, int out_size)
{
    const float* x     = (const float*)d_in[0];
    const float* Wq    = (const float*)d_in[1];
    const float* Wk    = (const float*)d_in[2];
    const float* Wv    = (const float*)d_in[3];
    const float* Wo    = (const float*)d_in[4];
    const float* gamma = (const float*)d_in[5];
    const float* beta  = (const float*)d_in[6];
    float* out = (float*)d_out;

    cudaFuncSetAttribute(qkv_gemm, cudaFuncAttributeMaxDynamicSharedMemorySize, GEMM_SMEM_BYTES);
    cudaFuncSetAttribute(out_gemm, cudaFuncAttributeMaxDynamicSharedMemorySize, GEMM_SMEM_BYTES);
    cudaFuncSetAttribute(flash_attn, cudaFuncAttributeMaxDynamicSharedMemorySize, FLASH_SMEM);

    dim3 g1(D / BN, NROWS / BM, 3);
    qkv_gemm<<<g1, 256, GEMM_SMEM_BYTES>>>(x, Wq, Wk, Wv);

    dim3 g2(L / AFM, H, B);
    flash_attn<<<g2, 256, FLASH_SMEM>>>();

    dim3 g3(D / BN, NROWS / BM);
    out_gemm<<<g3, 256, GEMM_SMEM_BYTES>>>(Wo, x, out);

    layernorm_kernel<<<NROWS, 256>>>(out, gamma, beta);
}

// round 5
// speedup vs baseline: 3.6336x; 1.5345x over previous
#include <cuda_runtime.h>
#include <cuda_bf16.h>
#include <mma.h>
#include <math.h>
#include <stdint.h>

using namespace nvcuda;

#define B 4
#define L 2048
#define D 1024
#define H 16
#define DH 64
#define NROWS (B * L)   // 8192

typedef __nv_bfloat16 bf16;

// ---------------- scratch (no allocations allowed) ----------------
__device__ bf16 g_q[(size_t)B * H * L * DH];   // [B][H][L][DH] bf16
__device__ bf16 g_k[(size_t)B * H * L * DH];
__device__ bf16 g_v[(size_t)B * H * L * DH];
__device__ bf16 g_z[(size_t)NROWS * D];        // [B*L][D] bf16

// ---------------- helpers ----------------
__device__ __forceinline__ uint2 pack4bf(float4 v) {
    __nv_bfloat162 lo = __float22bfloat162_rn(make_float2(v.x, v.y));
    __nv_bfloat162 hi = __float22bfloat162_rn(make_float2(v.z, v.w));
    uint2 u;
    u.x = *(unsigned int*)&lo;
    u.y = *(unsigned int*)&hi;
    return u;
}
__device__ __forceinline__ uint32_t pack2bf(float a, float b) {
    __nv_bfloat162 h2 = __float22bfloat162_rn(make_float2(a, b));
    return *(unsigned int*)&h2;
}
__device__ __forceinline__ uint32_t smem_u32(const void* p) {
    uint32_t a;
    asm("{ .reg .u64 t; cvta.to.shared.u64 t, %1; cvt.u32.u64 %0, t; }" : "=r"(a) : "l"(p));
    return a;
}
__device__ __forceinline__ void cp16(void* s, const void* g) {
    uint32_t sa = smem_u32(s);
    asm volatile("cp.async.cg.shared.global [%0], [%1], 16;" :: "r"(sa), "l"(g) : "memory");
}
__device__ __forceinline__ void cp_commit() {
    asm volatile("cp.async.commit_group;" ::: "memory");
}
template<int N>
__device__ __forceinline__ void cp_wait() {
    asm volatile("cp.async.wait_group %0;" :: "n"(N) : "memory");
}
__device__ __forceinline__ void ldsm4(uint32_t* r, const void* p) {
    uint32_t a = smem_u32(p);
    asm volatile("ldmatrix.sync.aligned.m8n8.x4.shared.b16 {%0,%1,%2,%3}, [%4];"
                 : "=r"(r[0]), "=r"(r[1]), "=r"(r[2]), "=r"(r[3]) : "r"(a));
}
__device__ __forceinline__ void ldsm4t(uint32_t* r, const void* p) {
    uint32_t a = smem_u32(p);
    asm volatile("ldmatrix.sync.aligned.m8n8.x4.trans.shared.b16 {%0,%1,%2,%3}, [%4];"
                 : "=r"(r[0]), "=r"(r[1]), "=r"(r[2]), "=r"(r[3]) : "r"(a));
}
__device__ __forceinline__ void mma16816(float* c, const uint32_t* a, uint32_t b0, uint32_t b1) {
    asm volatile(
        "mma.sync.aligned.m16n8k16.row.col.f32.bf16.bf16.f32 "
        "{%0,%1,%2,%3}, {%4,%5,%6,%7}, {%8,%9}, {%0,%1,%2,%3};"
        : "+f"(c[0]), "+f"(c[1]), "+f"(c[2]), "+f"(c[3])
        : "r"(a[0]), "r"(a[1]), "r"(a[2]), "r"(a[3]), "r"(b0), "r"(b1));
}

// ---------------- GEMM (bf16 wmma), 128x128 tile, BK=32, double-buffered ----------------
#define BM 128
#define BN 128
#define BKb 32
#define ALD 40
#define BLD 136
#define STAGE_LD 132
#define GEMM_SMEM_BYTES 67584

using FA  = wmma::fragment<wmma::matrix_a, 16, 16, 16, bf16, wmma::row_major>;
using FBr = wmma::fragment<wmma::matrix_b, 16, 16, 16, bf16, wmma::row_major>;
using FC  = wmma::fragment<wmma::accumulator, 16, 16, 16, float>;

template<bool A_BF16>
__device__ __forceinline__ void gemm_loop(
    const void* __restrict__ Av, const float* __restrict__ W,
    bf16* As, bf16* Bs, int row0, int col0, FC acc[4][2])
{
    const int tid = threadIdx.x;
    const int warp = tid >> 5;
    const int wm = warp >> 2;
    const int wn = warp & 3;

    #pragma unroll
    for (int i = 0; i < 4; i++)
        #pragma unroll
        for (int j = 0; j < 2; j++)
            wmma::fill_fragment(acc[i][j], 0.0f);

    const int NT = D / BKb;
    const size_t abuf = (size_t)BM * ALD;
    const size_t bbuf = (size_t)BKb * BLD;

    {
        if (A_BF16) {
            const bf16* A = (const bf16*)Av;
            #pragma unroll
            for (int rep = 0; rep < 2; rep++) {
                int idx = tid + rep * 256;
                int r = idx >> 2, c = (idx & 3) << 3;
                *(uint4*)(As + r * ALD + c) = *(const uint4*)(A + (size_t)(row0 + r) * D + c);
            }
        } else {
            const float* A = (const float*)Av;
            #pragma unroll
            for (int rep = 0; rep < 4; rep++) {
                int idx = tid + rep * 256;
                int r = idx >> 3, c = (idx & 7) << 2;
                float4 v = *(const float4*)(A + (size_t)(row0 + r) * D + c);
                *(uint2*)(As + r * ALD + c) = pack4bf(v);
            }
        }
        #pragma unroll
        for (int rep = 0; rep < 4; rep++) {
            int idx = tid + rep * 256;
            int r = idx >> 5, c = (idx & 31) << 2;
            float4 v = *(const float4*)(W + (size_t)r * D + col0 + c);
            *(uint2*)(Bs + r * BLD + c) = pack4bf(v);
        }
    }
    __syncthreads();

    for (int t = 0; t < NT; t++) {
        bf16* Ac = As + (t & 1) * abuf;
        bf16* Bc = Bs + (t & 1) * bbuf;
        bf16* An = As + ((t + 1) & 1) * abuf;
        bf16* Bn = Bs + ((t + 1) & 1) * bbuf;
        const int k0n = (t + 1) * BKb;
        const bool more = (t + 1 < NT);

        float4 rb[4];
        float4 rafp[4];
        uint4  rabf[2];
        if (more) {
            if (A_BF16) {
                const bf16* A = (const bf16*)Av;
                #pragma unroll
                for (int rep = 0; rep < 2; rep++) {
                    int idx = tid + rep * 256;
                    int r = idx >> 2, c = (idx & 3) << 3;
                    rabf[rep] = *(const uint4*)(A + (size_t)(row0 + r) * D + k0n + c);
                }
            } else {
                const float* A = (const float*)Av;
                #pragma unroll
                for (int rep = 0; rep < 4; rep++) {
                    int idx = tid + rep * 256;
                    int r = idx >> 3, c = (idx & 7) << 2;
                    rafp[rep] = *(const float4*)(A + (size_t)(row0 + r) * D + k0n + c);
                }
            }
            #pragma unroll
            for (int rep = 0; rep < 4; rep++) {
                int idx = tid + rep * 256;
                int r = idx >> 5, c = (idx & 31) << 2;
                rb[rep] = *(const float4*)(W + (size_t)(k0n + r) * D + col0 + c);
            }
        }

        #pragma unroll
        for (int kk = 0; kk < 2; kk++) {
            FA a[4];
            FBr b[2];
            #pragma unroll
            for (int i = 0; i < 4; i++)
                wmma::load_matrix_sync(a[i], Ac + (wm * 64 + i * 16) * ALD + kk * 16, ALD);
            #pragma unroll
            for (int j = 0; j < 2; j++)
                wmma::load_matrix_sync(b[j], Bc + (kk * 16) * BLD + wn * 32 + j * 16, BLD);
            #pragma unroll
            for (int i = 0; i < 4; i++)
                #pragma unroll
                for (int j = 0; j < 2; j++)
                    wmma::mma_sync(acc[i][j], a[i], b[j], acc[i][j]);
        }

        if (more) {
            if (A_BF16) {
                #pragma unroll
                for (int rep = 0; rep < 2; rep++) {
                    int idx = tid + rep * 256;
                    int r = idx >> 2, c = (idx & 3) << 3;
                    *(uint4*)(An + r * ALD + c) = rabf[rep];
                }
            } else {
                #pragma unroll
                for (int rep = 0; rep < 4; rep++) {
                    int idx = tid + rep * 256;
                    int r = idx >> 3, c = (idx & 7) << 2;
                    *(uint2*)(An + r * ALD + c) = pack4bf(rafp[rep]);
                }
            }
            #pragma unroll
            for (int rep = 0; rep < 4; rep++) {
                int idx = tid + rep * 256;
                int r = idx >> 5, c = (idx & 31) << 2;
                *(uint2*)(Bn + r * BLD + c) = pack4bf(rb[rep]);
            }
        }
        __syncthreads();
    }
}

// QKV projection: grid (8, 64, 3)
__global__ void __launch_bounds__(256) qkv_gemm(const float* __restrict__ x,
                         const float* __restrict__ Wq,
                         const float* __restrict__ Wk,
                         const float* __restrict__ Wv)
{
    extern __shared__ char smem[];
    bf16* As = (bf16*)smem;
    bf16* Bs = As + 2 * BM * ALD;

    const int row0 = blockIdx.y * BM;
    const int col0 = blockIdx.x * BN;
    const float* Wsel = (blockIdx.z == 0) ? Wq : (blockIdx.z == 1) ? Wk : Wv;
    bf16* Out = (blockIdx.z == 0) ? g_q : (blockIdx.z == 1) ? g_k : g_v;

    FC acc[4][2];
    gemm_loop<false>(x, Wsel, As, Bs, row0, col0, acc);

    float* stage = (float*)smem;
    const int warp = threadIdx.x >> 5;
    const int wm = warp >> 2, wn = warp & 3;
    #pragma unroll
    for (int i = 0; i < 4; i++)
        #pragma unroll
        for (int j = 0; j < 2; j++)
            wmma::store_matrix_sync(stage + (wm * 64 + i * 16) * STAGE_LD + wn * 32 + j * 16,
                                    acc[i][j], STAGE_LD, wmma::mem_row_major);
    __syncthreads();

    const int b = row0 / L;
    const int l0 = row0 % L;
    for (int idx = threadIdx.x; idx < BM * BN / 4; idx += 256) {
        int r = idx >> 5;
        int c = (idx & 31) << 2;
        float4 v = *(float4*)(stage + r * STAGE_LD + c);
        int gc = col0 + c;
        int h = gc >> 6;
        int d = gc & 63;
        bf16* dst = Out + (((size_t)(b * H + h) * L + l0 + r) * DH + d);
        *(uint2*)dst = pack4bf(v);
    }
}

// Output projection: z @ Wo + relu + residual. grid (8, 64)
__global__ void __launch_bounds__(256) out_gemm(const float* __restrict__ Wo,
                         const float* __restrict__ x,
                         float* __restrict__ out)
{
    extern __shared__ char smem[];
    bf16* As = (bf16*)smem;
    bf16* Bs = As + 2 * BM * ALD;

    const int row0 = blockIdx.y * BM;
    const int col0 = blockIdx.x * BN;

    FC acc[4][2];
    gemm_loop<true>(g_z, Wo, As, Bs, row0, col0, acc);

    float* stage = (float*)smem;
    const int warp = threadIdx.x >> 5;
    const int wm = warp >> 2, wn = warp & 3;
    #pragma unroll
    for (int i = 0; i < 4; i++)
        #pragma unroll
        for (int j = 0; j < 2; j++)
            wmma::store_matrix_sync(stage + (wm * 64 + i * 16) * STAGE_LD + wn * 32 + j * 16,
                                    acc[i][j], STAGE_LD, wmma::mem_row_major);
    __syncthreads();

    for (int idx = threadIdx.x; idx < BM * BN / 4; idx += 256) {
        int r = idx >> 5;
        int c = (idx & 31) << 2;
        float4 a = *(float4*)(stage + r * STAGE_LD + c);
        float4 xr = *(const float4*)(x + (size_t)(row0 + r) * D + col0 + c);
        a.x = fmaxf(a.x, 0.f) + xr.x;
        a.y = fmaxf(a.y, 0.f) + xr.y;
        a.z = fmaxf(a.z, 0.f) + xr.z;
        a.w = fmaxf(a.w, 0.f) + xr.w;
        *(float4*)(out + (size_t)(row0 + r) * D + col0 + c) = a;
    }
}

// ---------------- causal flash attention (mma.sync, fully register-resident) ----------------
#define AFM 128
#define AFN 64
#define QLD 72        // bf16 elems; 144B rows
#define KVLD 72
// smem: Q 128*72*2 = 18432; K 2 stages 64*72*2*2 = 18432; V same = 18432
#define FLASH_SMEM (18432 * 3)   // 55296

// grid (L/128, H, B), 256 threads = 8 warps; warp w owns query rows [16w,16w+16).
__global__ void __launch_bounds__(256) flash_attn()
{
    extern __shared__ char fsm[];
    bf16* Qs = (bf16*)fsm;
    bf16* K0 = Qs + AFM * QLD;
    bf16* K1 = K0 + AFN * KVLD;
    bf16* V0 = K1 + AFN * KVLD;
    bf16* V1 = V0 + AFN * KVLD;
    bf16* Kst[2] = {K0, K1};
    bf16* Vst[2] = {V0, V1};

    const int mt = blockIdx.x, hh = blockIdx.y, bb = blockIdx.z;
    const int tid = threadIdx.x;
    const int warp = tid >> 5;
    const int lane = tid & 31;
    const int m0 = mt * AFM;

    const size_t head_off = ((size_t)(bb * H + hh) * L) * DH;
    const bf16* Qg = g_q + head_off;
    const bf16* Kg = g_k + head_off;
    const bf16* Vg = g_v + head_off;

    // group 0: Q tile (128 rows x 8 16B-chunks = 1024 -> 4/thread)
    #pragma unroll
    for (int rep = 0; rep < 4; rep++) {
        int idx = tid + rep * 256;
        int r = idx >> 3, c = (idx & 7) << 3;
        cp16(Qs + r * QLD + c, Qg + (size_t)(m0 + r) * DH + c);
    }
    cp_commit();

    const int ntmax = (m0 + AFM - 1) / AFN;   // = 2*mt+1 >= 1

    // groups 1,2: KV stages 0 and 1
    #pragma unroll
    for (int st = 0; st < 2; st++) {
        const int n0 = st * AFN;
        #pragma unroll
        for (int rep = 0; rep < 2; rep++) {
            int idx = tid + rep * 256;
            int r = idx >> 3, c = (idx & 7) << 3;
            cp16(Kst[st] + r * KVLD + c, Kg + (size_t)(n0 + r) * DH + c);
            cp16(Vst[st] + r * KVLD + c, Vg + (size_t)(n0 + r) * DH + c);
        }
        cp_commit();
    }

    // wait for Q, load Q fragments (held in registers for whole loop)
    cp_wait<2>();
    __syncthreads();
    uint32_t qf[4][4];
    {
        const bf16* qa = Qs + (warp * 16 + (lane & 15)) * QLD + ((lane >> 4) << 3);
        #pragma unroll
        for (int kk = 0; kk < 4; kk++)
            ldsm4(qf[kk], qa + kk * 16);
    }

    const int g = lane >> 2;
    const int t4 = lane & 3;
    const int wrow0 = m0 + warp * 16;
    const int r0g = wrow0 + g;        // global rows this thread owns
    const int r1g = r0g + 8;

    float o[8][4];
    #pragma unroll
    for (int d = 0; d < 8; d++)
        #pragma unroll
        for (int e = 0; e < 4; e++) o[d][e] = 0.f;
    float m0r = -1e30f, m1r = -1e30f, l0 = 0.f, l1 = 0.f;

    for (int nt = 0; nt <= ntmax; nt++) {
        const int buf = nt & 1;
        const int n0 = nt * AFN;
        if (nt < ntmax) cp_wait<1>(); else cp_wait<0>();
        __syncthreads();

        if (n0 <= wrow0 + 15) {   // not fully masked for this warp
            bf16* Ks = Kst[buf];
            bf16* Vs = Vst[buf];

            // ---- S = Q K^T (16 x 64) ----
            float sc[8][4];
            #pragma unroll
            for (int j = 0; j < 8; j++)
                #pragma unroll
                for (int e = 0; e < 4; e++) sc[j][e] = 0.f;

            #pragma unroll
            for (int kk = 0; kk < 4; kk++) {
                #pragma unroll
                for (int jp = 0; jp < 4; jp++) {
                    uint32_t bfr[4];
                    int row = jp * 16 + (lane & 7) + ((lane >> 4) << 3);
                    int col = kk * 16 + (((lane >> 3) & 1) << 3);
                    ldsm4(bfr, Ks + row * KVLD + col);
                    mma16816(sc[2 * jp],     qf[kk], bfr[0], bfr[1]);
                    mma16816(sc[2 * jp + 1], qf[kk], bfr[2], bfr[3]);
                }
            }

            // ---- scale + mask + online softmax (registers + quad shfl) ----
            const bool diag = (n0 + 63 > wrow0);
            float mx0 = m0r, mx1 = m1r;
            #pragma unroll
            for (int j = 0; j < 8; j++) {
                const int c0 = n0 + j * 8 + 2 * t4;
                float s0 = sc[j][0] * 0.125f;
                float s1 = sc[j][1] * 0.125f;
                float s2 = sc[j][2] * 0.125f;
                float s3 = sc[j][3] * 0.125f;
                if (diag) {
                    s0 = (c0     <= r0g) ? s0 : -1e30f;
                    s1 = (c0 + 1 <= r0g) ? s1 : -1e30f;
                    s2 = (c0     <= r1g) ? s2 : -1e30f;
                    s3 = (c0 + 1 <= r1g) ? s3 : -1e30f;
                }
                sc[j][0] = s0; sc[j][1] = s1; sc[j][2] = s2; sc[j][3] = s3;
                mx0 = fmaxf(mx0, fmaxf(s0, s1));
                mx1 = fmaxf(mx1, fmaxf(s2, s3));
            }
            mx0 = fmaxf(mx0, __shfl_xor_sync(0xffffffffu, mx0, 1));
            mx0 = fmaxf(mx0, __shfl_xor_sync(0xffffffffu, mx0, 2));
            mx1 = fmaxf(mx1, __shfl_xor_sync(0xffffffffu, mx1, 1));
            mx1 = fmaxf(mx1, __shfl_xor_sync(0xffffffffu, mx1, 2));

            const float alpha0 = __expf(m0r - mx0);
            const float alpha1 = __expf(m1r - mx1);

            uint32_t pp0[8], pp1[8];
            float sum0 = 0.f, sum1 = 0.f;
            #pragma unroll
            for (int j = 0; j < 8; j++) {
                float p0 = __expf(sc[j][0] - mx0);
                float p1 = __expf(sc[j][1] - mx0);
                float p2 = __expf(sc[j][2] - mx1);
                float p3 = __expf(sc[j][3] - mx1);
                sum0 += p0 + p1;
                sum1 += p2 + p3;
                pp0[j] = pack2bf(p0, p1);   // row g, keys 2t4,2t4+1 of tile j
                pp1[j] = pack2bf(p2, p3);   // row g+8
            }
            sum0 += __shfl_xor_sync(0xffffffffu, sum0, 1);
            sum0 += __shfl_xor_sync(0xffffffffu, sum0, 2);
            sum1 += __shfl_xor_sync(0xffffffffu, sum1, 1);
            sum1 += __shfl_xor_sync(0xffffffffu, sum1, 2);

            l0 = l0 * alpha0 + sum0;
            l1 = l1 * alpha1 + sum1;
            m0r = mx0;
            m1r = mx1;

            #pragma unroll
            for (int d = 0; d < 8; d++) {
                o[d][0] *= alpha0; o[d][1] *= alpha0;
                o[d][2] *= alpha1; o[d][3] *= alpha1;
            }

            // ---- O += P V ----
            #pragma unroll
            for (int kt = 0; kt < 4; kt++) {
                uint32_t pa[4] = {pp0[2 * kt], pp1[2 * kt], pp0[2 * kt + 1], pp1[2 * kt + 1]};
                #pragma unroll
                for (int dp = 0; dp < 4; dp++) {
                    uint32_t bfr[4];
                    int row = kt * 16 + (lane & 15);
                    int col = dp * 16 + ((lane >> 4) << 3);
                    ldsm4t(bfr, Vs + row * KVLD + col);
                    mma16816(o[2 * dp],     pa, bfr[0], bfr[1]);
                    mma16816(o[2 * dp + 1], pa, bfr[2], bfr[3]);
                }
            }
        }
        __syncthreads();   // everyone done reading stage `buf`

        if (nt + 2 <= ntmax) {   // refill freed buffer
            const int nn0 = (nt + 2) * AFN;
            #pragma unroll
            for (int rep = 0; rep < 2; rep++) {
                int idx = tid + rep * 256;
                int r = idx >> 3, c = (idx & 7) << 3;
                cp16(Kst[buf] + r * KVLD + c, Kg + (size_t)(nn0 + r) * DH + c);
                cp16(Vst[buf] + r * KVLD + c, Vg + (size_t)(nn0 + r) * DH + c);
            }
            cp_commit();
        }
    }

    // epilogue: normalize, write z bf16 in [B*L][D] layout
    const float rl0 = 1.0f / l0;
    const float rl1 = 1.0f / l1;
    bf16* z0 = g_z + ((size_t)(bb * L + r0g)) * D + hh * DH;
    bf16* z1 = g_z + ((size_t)(bb * L + r1g)) * D + hh * DH;
    #pragma unroll
    for (int d = 0; d < 8; d++) {
        int c = d * 8 + 2 * t4;
        *(uint32_t*)(z0 + c) = pack2bf(o[d][0] * rl0, o[d][1] * rl0);
        *(uint32_t*)(z1 + c) = pack2bf(o[d][2] * rl1, o[d][3] * rl1);
    }
}

// ---------------- layernorm ----------------
__global__ void layernorm_kernel(float* __restrict__ out,
                                 const float* __restrict__ gamma,
                                 const float* __restrict__ beta)
{
    __shared__ float row[D];
    __shared__ float red[8];
    const int r = blockIdx.x;
    const int tid = threadIdx.x;
    float* o = out + (size_t)r * D;

    float s = 0.f;
    for (int c = tid; c < D; c += 256) {
        float v = o[c];
        row[c] = v;
        s += v;
    }
    {
        for (int off = 16; off; off >>= 1) s += __shfl_xor_sync(0xffffffffu, s, off);
        if ((tid & 31) == 0) red[tid >> 5] = s;
        __syncthreads();
        if (tid < 32) {
            float v = (tid < 8) ? red[tid] : 0.f;
            for (int off = 4; off; off >>= 1) v += __shfl_xor_sync(0xffffffffu, v, off);
            if (tid == 0) red[0] = v;
        }
        __syncthreads();
    }
    const float mu = red[0] * (1.0f / D);
    __syncthreads();

    float vs = 0.f;
    for (int c = tid; c < D; c += 256) {
        float d = row[c] - mu;
        vs += d * d;
    }
    {
        for (int off = 16; off; off >>= 1) vs += __shfl_xor_sync(0xffffffffu, vs, off);
        if ((tid & 31) == 0) red[tid >> 5] = vs;
        __syncthreads();
        if (tid < 32) {
            float v = (tid < 8) ? red[tid] : 0.f;
            for (int off = 4; off; off >>= 1) v += __shfl_xor_sync(0xffffffffu, v, off);
            if (tid == 0) red[0] = v;
        }
        __syncthreads();
    }
    const float inv = rsqrtf(red[0] * (1.0f / D) + 1e-12f);

    for (int c = tid; c < D; c += 256)
        o[c] = (row[c] - mu) * inv * gamma[c] + beta[c];
}

// ---------------- launch ----------------
extern "C" void kernel_launch(void* const* d_in, const int* in_sizes, int n_in,
                              void* d_out, int out_size)
{
    const float* x     = (const float*)d_in[0];
    const float* Wq    = (const float*)d_in[1];
    const float* Wk    = (const float*)d_in[2];
    const float* Wv    = (const float*)d_in[3];
    const float* Wo    = (const float*)d_in[4];
    const float* gamma = (const float*)d_in[5];
    const float* beta  = (const float*)d_in[6];
    float* out = (float*)d_out;

    cudaFuncSetAttribute(qkv_gemm, cudaFuncAttributeMaxDynamicSharedMemorySize, GEMM_SMEM_BYTES);
    cudaFuncSetAttribute(out_gemm, cudaFuncAttributeMaxDynamicSharedMemorySize, GEMM_SMEM_BYTES);
    cudaFuncSetAttribute(flash_attn, cudaFuncAttributeMaxDynamicSharedMemorySize, FLASH_SMEM);

    dim3 g1(D / BN, NROWS / BM, 3);
    qkv_gemm<<<g1, 256, GEMM_SMEM_BYTES>>>(x, Wq, Wk, Wv);

    dim3 g2(L / AFM, H, B);
    flash_attn<<<g2, 256, FLASH_SMEM>>>();

    dim3 g3(D / BN, NROWS / BM);
    out_gemm<<<g3, 256, GEMM_SMEM_BYTES>>>(Wo, x, out);

    layernorm_kernel<<<NROWS, 256>>>(out, gamma, beta);
}

// round 6
// speedup vs baseline: 5.1004x; 1.4037x over previous
#include <cuda_runtime.h>
#include <cuda_bf16.h>
#include <math.h>
#include <stdint.h>

#define B 4
#define L 2048
#define D 1024
#define H 16
#define DH 64
#define NROWS (B * L)   // 8192

typedef __nv_bfloat16 bf16;

// ---------------- scratch (no allocations allowed) ----------------
__device__ bf16 g_q[(size_t)B * H * L * DH];   // [B][H][L][DH] bf16
__device__ bf16 g_k[(size_t)B * H * L * DH];
__device__ bf16 g_v[(size_t)B * H * L * DH];
__device__ bf16 g_z[(size_t)NROWS * D];        // [B*L][D] bf16
__device__ bf16 g_xb[(size_t)NROWS * D];       // x bf16 [M,K]
__device__ bf16 g_wqkv[(size_t)3 * D * D];     // fused [Wq^T;Wk^T;Wv^T] bf16 [3072,1024] (n,k)
__device__ bf16 g_wot[(size_t)D * D];          // Wo^T bf16 [1024,1024]

// ---------------- helpers ----------------
__device__ __forceinline__ uint2 pack4bf(float4 v) {
    __nv_bfloat162 lo = __float22bfloat162_rn(make_float2(v.x, v.y));
    __nv_bfloat162 hi = __float22bfloat162_rn(make_float2(v.z, v.w));
    uint2 u;
    u.x = *(unsigned int*)&lo;
    u.y = *(unsigned int*)&hi;
    return u;
}
__device__ __forceinline__ uint32_t pack2bf(float a, float b) {
    __nv_bfloat162 h2 = __float22bfloat162_rn(make_float2(a, b));
    return *(unsigned int*)&h2;
}
__device__ __forceinline__ uint32_t smem_u32(const void* p) {
    uint32_t a;
    asm("{ .reg .u64 t; cvta.to.shared.u64 t, %1; cvt.u32.u64 %0, t; }" : "=r"(a) : "l"(p));
    return a;
}
__device__ __forceinline__ void cp16(void* s, const void* g) {
    uint32_t sa = smem_u32(s);
    asm volatile("cp.async.cg.shared.global [%0], [%1], 16;" :: "r"(sa), "l"(g) : "memory");
}
__device__ __forceinline__ void cp_commit() {
    asm volatile("cp.async.commit_group;" ::: "memory");
}
template<int N>
__device__ __forceinline__ void cp_wait() {
    asm volatile("cp.async.wait_group %0;" :: "n"(N) : "memory");
}
__device__ __forceinline__ void ldsm4(uint32_t* r, const void* p) {
    uint32_t a = smem_u32(p);
    asm volatile("ldmatrix.sync.aligned.m8n8.x4.shared.b16 {%0,%1,%2,%3}, [%4];"
                 : "=r"(r[0]), "=r"(r[1]), "=r"(r[2]), "=r"(r[3]) : "r"(a));
}
__device__ __forceinline__ void ldsm4t(uint32_t* r, const void* p) {
    uint32_t a = smem_u32(p);
    asm volatile("ldmatrix.sync.aligned.m8n8.x4.trans.shared.b16 {%0,%1,%2,%3}, [%4];"
                 : "=r"(r[0]), "=r"(r[1]), "=r"(r[2]), "=r"(r[3]) : "r"(a));
}
__device__ __forceinline__ void mma16816(float* c, const uint32_t* a, uint32_t b0, uint32_t b1) {
    asm volatile(
        "mma.sync.aligned.m16n8k16.row.col.f32.bf16.bf16.f32 "
        "{%0,%1,%2,%3}, {%4,%5,%6,%7}, {%8,%9}, {%0,%1,%2,%3};"
        : "+f"(c[0]), "+f"(c[1]), "+f"(c[2]), "+f"(c[3])
        : "r"(a[0]), "r"(a[1]), "r"(a[2]), "r"(a[3]), "r"(b0), "r"(b1));
}

// ---------------- one-shot converts ----------------
__global__ void convert_x(const float* __restrict__ x) {
    size_t i = (size_t)(blockIdx.x * blockDim.x + threadIdx.x) * 4;
    float4 v = *(const float4*)(x + i);
    *(uint2*)(g_xb + i) = pack4bf(v);
}

// W [k][n] fp32 -> W^T [n][k] bf16. grid (32,32,4), block (32,8)
__global__ void transpose_w(const float* __restrict__ Wq, const float* __restrict__ Wk,
                            const float* __restrict__ Wv, const float* __restrict__ Wo) {
    __shared__ float tile[32][33];
    const int z = blockIdx.z;
    const float* W = (z == 0) ? Wq : (z == 1) ? Wk : (z == 2) ? Wv : Wo;
    bf16* T = (z < 3) ? (g_wqkv + (size_t)z * D * D) : g_wot;
    int x0 = blockIdx.x * 32, y0 = blockIdx.y * 32;
    int tx = threadIdx.x, ty = threadIdx.y;
    #pragma unroll
    for (int i = 0; i < 4; i++)
        tile[ty + i * 8][tx] = W[(size_t)(y0 + ty + i * 8) * D + x0 + tx];
    __syncthreads();
    #pragma unroll
    for (int i = 0; i < 4; i++)
        T[(size_t)(x0 + ty + i * 8) * D + y0 + tx] = __float2bfloat16(tile[tx][ty + i * 8]);
}

// ---------------- mma.sync GEMM: 128x256 CTA tile, BK=32, 3-stage cp.async ----------------
#define GBM 128
#define GBN 256
#define GBK 32
#define GALD 40                     // smem row stride (bf16): 80B, ldmatrix conflict-free
#define GA_STAGE (GBM * GALD)       // elems
#define GB_STAGE (GBN * GALD)
#define GEMM_SMEM ((GA_STAGE + GB_STAGE) * 3 * 2)   // 92160 B

// 256 threads = 8 warps; warp grid 2(M) x 4(N); warp tile 64x64.
// acc[i][j][4]: i = m16 tile (0..3), j = n8 tile (0..7).
__device__ __forceinline__ void gemm_mainloop(
    const bf16* __restrict__ Ag, const bf16* __restrict__ Bt,
    bf16* As, bf16* Bs, int row0, int col0, float acc[4][8][4])
{
    const int tid = threadIdx.x;
    const int warp = tid >> 5;
    const int lane = tid & 31;
    const int wm = warp >> 2;
    const int wn = warp & 3;

    #pragma unroll
    for (int i = 0; i < 4; i++)
        #pragma unroll
        for (int j = 0; j < 8; j++)
            #pragma unroll
            for (int e = 0; e < 4; e++) acc[i][j][e] = 0.f;

    const int NT = D / GBK;   // 32

    // prologue: stages 0..2
    #pragma unroll
    for (int s = 0; s < 3; s++) {
        const int k0 = s * GBK;
        bf16* A = As + s * GA_STAGE;
        bf16* Bst = Bs + s * GB_STAGE;
        #pragma unroll
        for (int rep = 0; rep < 2; rep++) {
            int idx = tid + rep * 256;
            int r = idx >> 2, c = idx & 3;
            cp16(A + r * GALD + c * 8, Ag + (size_t)(row0 + r) * D + k0 + c * 8);
        }
        #pragma unroll
        for (int rep = 0; rep < 4; rep++) {
            int idx = tid + rep * 256;
            int r = idx >> 2, c = idx & 3;
            cp16(Bst + r * GALD + c * 8, Bt + (size_t)(col0 + r) * D + k0 + c * 8);
        }
        cp_commit();
    }

    for (int t = 0; t < NT; t++) {
        cp_wait<2>();
        __syncthreads();
        const int s = t % 3;
        const bf16* A = As + s * GA_STAGE;
        const bf16* Bst = Bs + s * GB_STAGE;

        #pragma unroll
        for (int ks = 0; ks < 2; ks++) {
            uint32_t af[4][4];
            #pragma unroll
            for (int i = 0; i < 4; i++)
                ldsm4(af[i], A + (wm * 64 + i * 16 + (lane & 15)) * GALD
                             + ks * 16 + ((lane >> 4) << 3));
            #pragma unroll
            for (int jp = 0; jp < 4; jp++) {
                uint32_t bfr[4];
                ldsm4(bfr, Bst + (wn * 64 + jp * 16 + (lane & 7) + ((lane >> 4) << 3)) * GALD
                           + ks * 16 + (((lane >> 3) & 1) << 3));
                #pragma unroll
                for (int i = 0; i < 4; i++) {
                    mma16816(acc[i][2 * jp],     af[i], bfr[0], bfr[1]);
                    mma16816(acc[i][2 * jp + 1], af[i], bfr[2], bfr[3]);
                }
            }
        }
        __syncthreads();

        if (t + 3 < NT) {   // refill freed stage
            const int k0 = (t + 3) * GBK;
            bf16* An = As + s * GA_STAGE;
            bf16* Bn = Bs + s * GB_STAGE;
            #pragma unroll
            for (int rep = 0; rep < 2; rep++) {
                int idx = tid + rep * 256;
                int r = idx >> 2, c = idx & 3;
                cp16(An + r * GALD + c * 8, Ag + (size_t)(row0 + r) * D + k0 + c * 8);
            }
            #pragma unroll
            for (int rep = 0; rep < 4; rep++) {
                int idx = tid + rep * 256;
                int r = idx >> 2, c = idx & 3;
                cp16(Bn + r * GALD + c * 8, Bt + (size_t)(col0 + r) * D + k0 + c * 8);
            }
        }
        cp_commit();
    }
}

// fused QKV: grid (12, 64). col space = [Wq | Wk | Wv] (3072 wide).
__global__ void __launch_bounds__(256, 1) qkv_gemm()
{
    extern __shared__ char smem[];
    bf16* As = (bf16*)smem;
    bf16* Bs = As + 3 * GA_STAGE;

    const int row0 = blockIdx.y * GBM;
    const int col0 = blockIdx.x * GBN;

    float acc[4][8][4];
    gemm_mainloop(g_xb, g_wqkv, As, Bs, row0, col0, acc);

    const int warp = threadIdx.x >> 5;
    const int lane = threadIdx.x & 31;
    const int wm = warp >> 2, wn = warp & 3;
    const int g = lane >> 2, t4 = lane & 3;

    #pragma unroll
    for (int i = 0; i < 4; i++) {
        const int r0 = row0 + wm * 64 + i * 16 + g;
        const int b = r0 >> 11, l = r0 & 2047;
        #pragma unroll
        for (int j = 0; j < 8; j++) {
            int gcol = col0 + wn * 64 + j * 8 + 2 * t4;
            int sel = gcol >> 10;
            int hc = gcol & 1023;
            int h = hc >> 6, d = hc & 63;
            bf16* Out = (sel == 0) ? g_q : (sel == 1) ? g_k : g_v;
            size_t base = ((size_t)(b * H + h) * L + l) * DH + d;
            *(uint32_t*)(Out + base)            = pack2bf(acc[i][j][0], acc[i][j][1]);
            *(uint32_t*)(Out + base + 8 * DH)   = pack2bf(acc[i][j][2], acc[i][j][3]);
        }
    }
}

// out projection: grid (4, 64); fused relu + residual, fp32 out.
__global__ void __launch_bounds__(256, 1) out_gemm(const float* __restrict__ x,
                                                   float* __restrict__ out)
{
    extern __shared__ char smem[];
    bf16* As = (bf16*)smem;
    bf16* Bs = As + 3 * GA_STAGE;

    const int row0 = blockIdx.y * GBM;
    const int col0 = blockIdx.x * GBN;

    float acc[4][8][4];
    gemm_mainloop(g_z, g_wot, As, Bs, row0, col0, acc);

    const int warp = threadIdx.x >> 5;
    const int lane = threadIdx.x & 31;
    const int wm = warp >> 2, wn = warp & 3;
    const int g = lane >> 2, t4 = lane & 3;

    #pragma unroll
    for (int i = 0; i < 4; i++) {
        const int r0 = row0 + wm * 64 + i * 16 + g;
        #pragma unroll
        for (int j = 0; j < 8; j++) {
            int gcol = col0 + wn * 64 + j * 8 + 2 * t4;
            {
                float2 xv = *(const float2*)(x + (size_t)r0 * D + gcol);
                float2 o;
                o.x = fmaxf(acc[i][j][0], 0.f) + xv.x;
                o.y = fmaxf(acc[i][j][1], 0.f) + xv.y;
                *(float2*)(out + (size_t)r0 * D + gcol) = o;
            }
            {
                float2 xv = *(const float2*)(x + (size_t)(r0 + 8) * D + gcol);
                float2 o;
                o.x = fmaxf(acc[i][j][2], 0.f) + xv.x;
                o.y = fmaxf(acc[i][j][3], 0.f) + xv.y;
                *(float2*)(out + (size_t)(r0 + 8) * D + gcol) = o;
            }
        }
    }
}

// ---------------- causal flash attention (mma.sync, register-resident) ----------------
#define AFM 128
#define AFN 64
#define QLD 72
#define KVLD 72
#define FLASH_SMEM (18432 * 3)   // 55296

__global__ void __launch_bounds__(256) flash_attn()
{
    extern __shared__ char fsm[];
    bf16* Qs = (bf16*)fsm;
    bf16* K0 = Qs + AFM * QLD;
    bf16* K1 = K0 + AFN * KVLD;
    bf16* V0 = K1 + AFN * KVLD;
    bf16* V1 = V0 + AFN * KVLD;
    bf16* Kst[2] = {K0, K1};
    bf16* Vst[2] = {V0, V1};

    const int mt = blockIdx.x, hh = blockIdx.y, bb = blockIdx.z;
    const int tid = threadIdx.x;
    const int warp = tid >> 5;
    const int lane = tid & 31;
    const int m0 = mt * AFM;

    const size_t head_off = ((size_t)(bb * H + hh) * L) * DH;
    const bf16* Qg = g_q + head_off;
    const bf16* Kg = g_k + head_off;
    const bf16* Vg = g_v + head_off;

    #pragma unroll
    for (int rep = 0; rep < 4; rep++) {
        int idx = tid + rep * 256;
        int r = idx >> 3, c = (idx & 7) << 3;
        cp16(Qs + r * QLD + c, Qg + (size_t)(m0 + r) * DH + c);
    }
    cp_commit();

    const int ntmax = (m0 + AFM - 1) / AFN;

    #pragma unroll
    for (int st = 0; st < 2; st++) {
        const int n0 = st * AFN;
        #pragma unroll
        for (int rep = 0; rep < 2; rep++) {
            int idx = tid + rep * 256;
            int r = idx >> 3, c = (idx & 7) << 3;
            cp16(Kst[st] + r * KVLD + c, Kg + (size_t)(n0 + r) * DH + c);
            cp16(Vst[st] + r * KVLD + c, Vg + (size_t)(n0 + r) * DH + c);
        }
        cp_commit();
    }

    cp_wait<2>();
    __syncthreads();
    uint32_t qf[4][4];
    {
        const bf16* qa = Qs + (warp * 16 + (lane & 15)) * QLD + ((lane >> 4) << 3);
        #pragma unroll
        for (int kk = 0; kk < 4; kk++)
            ldsm4(qf[kk], qa + kk * 16);
    }

    const int g = lane >> 2;
    const int t4 = lane & 3;
    const int wrow0 = m0 + warp * 16;
    const int r0g = wrow0 + g;
    const int r1g = r0g + 8;

    float o[8][4];
    #pragma unroll
    for (int d = 0; d < 8; d++)
        #pragma unroll
        for (int e = 0; e < 4; e++) o[d][e] = 0.f;
    float m0r = -1e30f, m1r = -1e30f, l0 = 0.f, l1 = 0.f;

    for (int nt = 0; nt <= ntmax; nt++) {
        const int buf = nt & 1;
        const int n0 = nt * AFN;
        if (nt < ntmax) cp_wait<1>(); else cp_wait<0>();
        __syncthreads();

        if (n0 <= wrow0 + 15) {
            bf16* Ks = Kst[buf];
            bf16* Vs = Vst[buf];

            float sc[8][4];
            #pragma unroll
            for (int j = 0; j < 8; j++)
                #pragma unroll
                for (int e = 0; e < 4; e++) sc[j][e] = 0.f;

            #pragma unroll
            for (int kk = 0; kk < 4; kk++) {
                #pragma unroll
                for (int jp = 0; jp < 4; jp++) {
                    uint32_t bfr[4];
                    int row = jp * 16 + (lane & 7) + ((lane >> 4) << 3);
                    int col = kk * 16 + (((lane >> 3) & 1) << 3);
                    ldsm4(bfr, Ks + row * KVLD + col);
                    mma16816(sc[2 * jp],     qf[kk], bfr[0], bfr[1]);
                    mma16816(sc[2 * jp + 1], qf[kk], bfr[2], bfr[3]);
                }
            }

            const bool diag = (n0 + 63 > wrow0);
            float mx0 = m0r, mx1 = m1r;
            #pragma unroll
            for (int j = 0; j < 8; j++) {
                const int c0 = n0 + j * 8 + 2 * t4;
                float s0 = sc[j][0] * 0.125f;
                float s1 = sc[j][1] * 0.125f;
                float s2 = sc[j][2] * 0.125f;
                float s3 = sc[j][3] * 0.125f;
                if (diag) {
                    s0 = (c0     <= r0g) ? s0 : -1e30f;
                    s1 = (c0 + 1 <= r0g) ? s1 : -1e30f;
                    s2 = (c0     <= r1g) ? s2 : -1e30f;
                    s3 = (c0 + 1 <= r1g) ? s3 : -1e30f;
                }
                sc[j][0] = s0; sc[j][1] = s1; sc[j][2] = s2; sc[j][3] = s3;
                mx0 = fmaxf(mx0, fmaxf(s0, s1));
                mx1 = fmaxf(mx1, fmaxf(s2, s3));
            }
            mx0 = fmaxf(mx0, __shfl_xor_sync(0xffffffffu, mx0, 1));
            mx0 = fmaxf(mx0, __shfl_xor_sync(0xffffffffu, mx0, 2));
            mx1 = fmaxf(mx1, __shfl_xor_sync(0xffffffffu, mx1, 1));
            mx1 = fmaxf(mx1, __shfl_xor_sync(0xffffffffu, mx1, 2));

            const float alpha0 = __expf(m0r - mx0);
            const float alpha1 = __expf(m1r - mx1);

            uint32_t pp0[8], pp1[8];
            float sum0 = 0.f, sum1 = 0.f;
            #pragma unroll
            for (int j = 0; j < 8; j++) {
                float p0 = __expf(sc[j][0] - mx0);
                float p1 = __expf(sc[j][1] - mx0);
                float p2 = __expf(sc[j][2] - mx1);
                float p3 = __expf(sc[j][3] - mx1);
                sum0 += p0 + p1;
                sum1 += p2 + p3;
                pp0[j] = pack2bf(p0, p1);
                pp1[j] = pack2bf(p2, p3);
            }
            sum0 += __shfl_xor_sync(0xffffffffu, sum0, 1);
            sum0 += __shfl_xor_sync(0xffffffffu, sum0, 2);
            sum1 += __shfl_xor_sync(0xffffffffu, sum1, 1);
            sum1 += __shfl_xor_sync(0xffffffffu, sum1, 2);

            l0 = l0 * alpha0 + sum0;
            l1 = l1 * alpha1 + sum1;
            m0r = mx0;
            m1r = mx1;

            #pragma unroll
            for (int d = 0; d < 8; d++) {
                o[d][0] *= alpha0; o[d][1] *= alpha0;
                o[d][2] *= alpha1; o[d][3] *= alpha1;
            }

            #pragma unroll
            for (int kt = 0; kt < 4; kt++) {
                uint32_t pa[4] = {pp0[2 * kt], pp1[2 * kt], pp0[2 * kt + 1], pp1[2 * kt + 1]};
                #pragma unroll
                for (int dp = 0; dp < 4; dp++) {
                    uint32_t bfr[4];
                    int row = kt * 16 + (lane & 15);
                    int col = dp * 16 + ((lane >> 4) << 3);
                    ldsm4t(bfr, Vs + row * KVLD + col);
                    mma16816(o[2 * dp],     pa, bfr[0], bfr[1]);
                    mma16816(o[2 * dp + 1], pa, bfr[2], bfr[3]);
                }
            }
        }
        __syncthreads();

        if (nt + 2 <= ntmax) {
            const int nn0 = (nt + 2) * AFN;
            #pragma unroll
            for (int rep = 0; rep < 2; rep++) {
                int idx = tid + rep * 256;
                int r = idx >> 3, c = (idx & 7) << 3;
                cp16(Kst[buf] + r * KVLD + c, Kg + (size_t)(nn0 + r) * DH + c);
                cp16(Vst[buf] + r * KVLD + c, Vg + (size_t)(nn0 + r) * DH + c);
            }
            cp_commit();
        }
    }

    const float rl0 = 1.0f / l0;
    const float rl1 = 1.0f / l1;
    bf16* z0 = g_z + ((size_t)(bb * L + r0g)) * D + hh * DH;
    bf16* z1 = g_z + ((size_t)(bb * L + r1g)) * D + hh * DH;
    #pragma unroll
    for (int d = 0; d < 8; d++) {
        int c = d * 8 + 2 * t4;
        *(uint32_t*)(z0 + c) = pack2bf(o[d][0] * rl0, o[d][1] * rl0);
        *(uint32_t*)(z1 + c) = pack2bf(o[d][2] * rl1, o[d][3] * rl1);
    }
}

// ---------------- layernorm ----------------
__global__ void layernorm_kernel(float* __restrict__ out,
                                 const float* __restrict__ gamma,
                                 const float* __restrict__ beta)
{
    __shared__ float row[D];
    __shared__ float red[8];
    const int r = blockIdx.x;
    const int tid = threadIdx.x;
    float* o = out + (size_t)r * D;

    float s = 0.f;
    for (int c = tid; c < D; c += 256) {
        float v = o[c];
        row[c] = v;
        s += v;
    }
    {
        for (int off = 16; off; off >>= 1) s += __shfl_xor_sync(0xffffffffu, s, off);
        if ((tid & 31) == 0) red[tid >> 5] = s;
        __syncthreads();
        if (tid < 32) {
            float v = (tid < 8) ? red[tid] : 0.f;
            for (int off = 4; off; off >>= 1) v += __shfl_xor_sync(0xffffffffu, v, off);
            if (tid == 0) red[0] = v;
        }
        __syncthreads();
    }
    const float mu = red[0] * (1.0f / D);
    __syncthreads();

    float vs = 0.f;
    for (int c = tid; c < D; c += 256) {
        float d = row[c] - mu;
        vs += d * d;
    }
    {
        for (int off = 16; off; off >>= 1) vs += __shfl_xor_sync(0xffffffffu, vs, off);
        if ((tid & 31) == 0) red[tid >> 5] = vs;
        __syncthreads();
        if (tid < 32) {
            float v = (tid < 8) ? red[tid] : 0.f;
            for (int off = 4; off; off >>= 1) v += __shfl_xor_sync(0xffffffffu, v, off);
            if (tid == 0) red[0] = v;
        }
        __syncthreads();
    }
    const float inv = rsqrtf(red[0] * (1.0f / D) + 1e-12f);

    for (int c = tid; c < D; c += 256)
        o[c] = (row[c] - mu) * inv * gamma[c] + beta[c];
}

// ---------------- launch ----------------
extern "C" void kernel_launch(void* const* d_in, const int* in_sizes, int n_in,
                              void* d_out, int out_size)
{
    const float* x     = (const float*)d_in[0];
    const float* Wq    = (const float*)d_in[1];
    const float* Wk    = (const float*)d_in[2];
    const float* Wv    = (const float*)d_in[3];
    const float* Wo    = (const float*)d_in[4];
    const float* gamma = (const float*)d_in[5];
    const float* beta  = (const float*)d_in[6];
    float* out = (float*)d_out;

    cudaFuncSetAttribute(qkv_gemm, cudaFuncAttributeMaxDynamicSharedMemorySize, GEMM_SMEM);
    cudaFuncSetAttribute(out_gemm, cudaFuncAttributeMaxDynamicSharedMemorySize, GEMM_SMEM);
    cudaFuncSetAttribute(flash_attn, cudaFuncAttributeMaxDynamicSharedMemorySize, FLASH_SMEM);

    convert_x<<<NROWS * D / 4 / 256, 256>>>(x);
    transpose_w<<<dim3(32, 32, 4), dim3(32, 8)>>>(Wq, Wk, Wv, Wo);

    qkv_gemm<<<dim3(3 * D / GBN, NROWS / GBM), 256, GEMM_SMEM>>>();

    flash_attn<<<dim3(L / AFM, H, B), 256, FLASH_SMEM>>>();

    out_gemm<<<dim3(D / GBN, NROWS / GBM), 256, GEMM_SMEM>>>(x, out);

    layernorm_kernel<<<NROWS, 256>>>(out, gamma, beta);
}

// round 8
// speedup vs baseline: 5.4196x; 1.0626x over previous
#include <cuda_runtime.h>
#include <cuda_bf16.h>
#include <math.h>
#include <stdint.h>

#define B 4
#define L 2048
#define D 1024
#define H 16
#define DH 64
#define NROWS (B * L)   // 8192

typedef __nv_bfloat16 bf16;

// ---------------- scratch (no allocations allowed) ----------------
__device__ bf16 g_q[(size_t)B * H * L * DH];
__device__ bf16 g_k[(size_t)B * H * L * DH];
__device__ bf16 g_v[(size_t)B * H * L * DH];
__device__ bf16 g_z[(size_t)NROWS * D];
__device__ bf16 g_xb[(size_t)NROWS * D];
__device__ bf16 g_wqkv[(size_t)3 * D * D];     // [Wq^T;Wk^T;Wv^T] bf16 [3072,1024] (n,k)
__device__ bf16 g_wot[(size_t)D * D];          // Wo^T bf16

// ---------------- helpers ----------------
__device__ __forceinline__ uint2 pack4bf(float4 v) {
    __nv_bfloat162 lo = __float22bfloat162_rn(make_float2(v.x, v.y));
    __nv_bfloat162 hi = __float22bfloat162_rn(make_float2(v.z, v.w));
    uint2 u;
    u.x = *(unsigned int*)&lo;
    u.y = *(unsigned int*)&hi;
    return u;
}
__device__ __forceinline__ uint32_t pack2bf(float a, float b) {
    __nv_bfloat162 h2 = __float22bfloat162_rn(make_float2(a, b));
    return *(unsigned int*)&h2;
}
__device__ __forceinline__ uint32_t smem_u32(const void* p) {
    uint32_t a;
    asm("{ .reg .u64 t; cvta.to.shared.u64 t, %1; cvt.u32.u64 %0, t; }" : "=r"(a) : "l"(p));
    return a;
}
__device__ __forceinline__ void cp16(void* s, const void* g) {
    uint32_t sa = smem_u32(s);
    asm volatile("cp.async.cg.shared.global [%0], [%1], 16;" :: "r"(sa), "l"(g) : "memory");
}
__device__ __forceinline__ void cp_commit() {
    asm volatile("cp.async.commit_group;" ::: "memory");
}
template<int N>
__device__ __forceinline__ void cp_wait() {
    asm volatile("cp.async.wait_group %0;" :: "n"(N) : "memory");
}
__device__ __forceinline__ void ldsm4(uint32_t* r, const void* p) {
    uint32_t a = smem_u32(p);
    asm volatile("ldmatrix.sync.aligned.m8n8.x4.shared.b16 {%0,%1,%2,%3}, [%4];"
                 : "=r"(r[0]), "=r"(r[1]), "=r"(r[2]), "=r"(r[3]) : "r"(a));
}
__device__ __forceinline__ void ldsm4t(uint32_t* r, const void* p) {
    uint32_t a = smem_u32(p);
    asm volatile("ldmatrix.sync.aligned.m8n8.x4.trans.shared.b16 {%0,%1,%2,%3}, [%4];"
                 : "=r"(r[0]), "=r"(r[1]), "=r"(r[2]), "=r"(r[3]) : "r"(a));
}
__device__ __forceinline__ void mma16816(float* c, const uint32_t* a, uint32_t b0, uint32_t b1) {
    asm volatile(
        "mma.sync.aligned.m16n8k16.row.col.f32.bf16.bf16.f32 "
        "{%0,%1,%2,%3}, {%4,%5,%6,%7}, {%8,%9}, {%0,%1,%2,%3};"
        : "+f"(c[0]), "+f"(c[1]), "+f"(c[2]), "+f"(c[3])
        : "r"(a[0]), "r"(a[1]), "r"(a[2]), "r"(a[3]), "r"(b0), "r"(b1));
}

// ---------------- one-shot converts ----------------
__global__ void convert_x(const float* __restrict__ x) {
    size_t i = (size_t)(blockIdx.x * blockDim.x + threadIdx.x) * 4;
    float4 v = *(const float4*)(x + i);
    *(uint2*)(g_xb + i) = pack4bf(v);
}

__global__ void transpose_w(const float* __restrict__ Wq, const float* __restrict__ Wk,
                            const float* __restrict__ Wv, const float* __restrict__ Wo) {
    __shared__ float tile[32][33];
    const int z = blockIdx.z;
    const float* W = (z == 0) ? Wq : (z == 1) ? Wk : (z == 2) ? Wv : Wo;
    bf16* T = (z < 3) ? (g_wqkv + (size_t)z * D * D) : g_wot;
    int x0 = blockIdx.x * 32, y0 = blockIdx.y * 32;
    int tx = threadIdx.x, ty = threadIdx.y;
    #pragma unroll
    for (int i = 0; i < 4; i++)
        tile[ty + i * 8][tx] = W[(size_t)(y0 + ty + i * 8) * D + x0 + tx];
    __syncthreads();
    #pragma unroll
    for (int i = 0; i < 4; i++)
        T[(size_t)(x0 + ty + i * 8) * D + y0 + tx] = __float2bfloat16(tile[tx][ty + i * 8]);
}

// ---------------- mma.sync GEMM: 128x256 tile, 512 threads (16 warps), warp 64x32 ----------------
#define GBM 128
#define GBN 256
#define GBK 32
#define GALD 40
#define GA_STAGE (GBM * GALD)
#define GB_STAGE (GBN * GALD)
#define GEMM_SMEM ((GA_STAGE + GB_STAGE) * 3 * 2)   // 92160 B

// warp grid 2(M) x 8(N); acc[i 0..3][j 0..3][4]
__device__ __forceinline__ void gemm_mainloop(
    const bf16* __restrict__ Ag, const bf16* __restrict__ Bt,
    bf16* As, bf16* Bs, int row0, int col0, float acc[4][4][4])
{
    const int tid = threadIdx.x;
    const int warp = tid >> 5;
    const int lane = tid & 31;
    const int wm = warp >> 3;    // 0..1
    const int wn = warp & 7;     // 0..7

    #pragma unroll
    for (int i = 0; i < 4; i++)
        #pragma unroll
        for (int j = 0; j < 4; j++)
            #pragma unroll
            for (int e = 0; e < 4; e++) acc[i][j][e] = 0.f;

    const int NT = D / GBK;   // 32

    #pragma unroll
    for (int s = 0; s < 3; s++) {
        const int k0 = s * GBK;
        bf16* A = As + s * GA_STAGE;
        bf16* Bst = Bs + s * GB_STAGE;
        {
            int r = tid >> 2, c = tid & 3;
            cp16(A + r * GALD + c * 8, Ag + (size_t)(row0 + r) * D + k0 + c * 8);
        }
        #pragma unroll
        for (int rep = 0; rep < 2; rep++) {
            int idx = tid + rep * 512;
            int r = idx >> 2, c = idx & 3;
            cp16(Bst + r * GALD + c * 8, Bt + (size_t)(col0 + r) * D + k0 + c * 8);
        }
        cp_commit();
    }

    for (int t = 0; t < NT; t++) {
        cp_wait<2>();
        __syncthreads();
        const int s = t % 3;
        const bf16* A = As + s * GA_STAGE;
        const bf16* Bst = Bs + s * GB_STAGE;

        #pragma unroll
        for (int ks = 0; ks < 2; ks++) {
            uint32_t af[4][4];
            #pragma unroll
            for (int i = 0; i < 4; i++)
                ldsm4(af[i], A + (wm * 64 + i * 16 + (lane & 15)) * GALD
                             + ks * 16 + ((lane >> 4) << 3));
            #pragma unroll
            for (int jp = 0; jp < 2; jp++) {
                uint32_t bfr[4];
                ldsm4(bfr, Bst + (wn * 32 + jp * 16 + (lane & 7) + ((lane >> 4) << 3)) * GALD
                           + ks * 16 + (((lane >> 3) & 1) << 3));
                #pragma unroll
                for (int i = 0; i < 4; i++) {
                    mma16816(acc[i][2 * jp],     af[i], bfr[0], bfr[1]);
                    mma16816(acc[i][2 * jp + 1], af[i], bfr[2], bfr[3]);
                }
            }
        }
        __syncthreads();

        if (t + 3 < NT) {
            const int k0 = (t + 3) * GBK;
            bf16* An = As + s * GA_STAGE;
            bf16* Bn = Bs + s * GB_STAGE;
            {
                int r = tid >> 2, c = tid & 3;
                cp16(An + r * GALD + c * 8, Ag + (size_t)(row0 + r) * D + k0 + c * 8);
            }
            #pragma unroll
            for (int rep = 0; rep < 2; rep++) {
                int idx = tid + rep * 512;
                int r = idx >> 2, c = idx & 3;
                cp16(Bn + r * GALD + c * 8, Bt + (size_t)(col0 + r) * D + k0 + c * 8);
            }
        }
        cp_commit();
    }
}

// fused QKV: grid (12, 64), 512 threads
__global__ void __launch_bounds__(512, 1) qkv_gemm()
{
    extern __shared__ char smem[];
    bf16* As = (bf16*)smem;
    bf16* Bs = As + 3 * GA_STAGE;

    const int row0 = blockIdx.y * GBM;
    const int col0 = blockIdx.x * GBN;

    float acc[4][4][4];
    gemm_mainloop(g_xb, g_wqkv, As, Bs, row0, col0, acc);

    const int warp = threadIdx.x >> 5;
    const int lane = threadIdx.x & 31;
    const int wm = warp >> 3, wn = warp & 7;
    const int g = lane >> 2, t4 = lane & 3;

    #pragma unroll
    for (int i = 0; i < 4; i++) {
        const int r0 = row0 + wm * 64 + i * 16 + g;
        const int b = r0 >> 11, l = r0 & 2047;
        #pragma unroll
        for (int j = 0; j < 4; j++) {
            int gcol = col0 + wn * 32 + j * 8 + 2 * t4;
            int sel = gcol >> 10;
            int hc = gcol & 1023;
            int h = hc >> 6, d = hc & 63;
            bf16* Out = (sel == 0) ? g_q : (sel == 1) ? g_k : g_v;
            size_t base = ((size_t)(b * H + h) * L + l) * DH + d;
            *(uint32_t*)(Out + base)          = pack2bf(acc[i][j][0], acc[i][j][1]);
            *(uint32_t*)(Out + base + 8 * DH) = pack2bf(acc[i][j][2], acc[i][j][3]);
        }
    }
}

// out projection: grid (4, 64), 512 threads; fused relu + residual
__global__ void __launch_bounds__(512, 1) out_gemm(const float* __restrict__ x,
                                                   float* __restrict__ out)
{
    extern __shared__ char smem[];
    bf16* As = (bf16*)smem;
    bf16* Bs = As + 3 * GA_STAGE;

    const int row0 = blockIdx.y * GBM;
    const int col0 = blockIdx.x * GBN;

    float acc[4][4][4];
    gemm_mainloop(g_z, g_wot, As, Bs, row0, col0, acc);

    const int warp = threadIdx.x >> 5;
    const int lane = threadIdx.x & 31;
    const int wm = warp >> 3, wn = warp & 7;
    const int g = lane >> 2, t4 = lane & 3;

    #pragma unroll
    for (int i = 0; i < 4; i++) {
        const int r0 = row0 + wm * 64 + i * 16 + g;
        #pragma unroll
        for (int j = 0; j < 4; j++) {
            int gcol = col0 + wn * 32 + j * 8 + 2 * t4;
            {
                float2 xv = *(const float2*)(x + (size_t)r0 * D + gcol);
                float2 o;
                o.x = fmaxf(acc[i][j][0], 0.f) + xv.x;
                o.y = fmaxf(acc[i][j][1], 0.f) + xv.y;
                *(float2*)(out + (size_t)r0 * D + gcol) = o;
            }
            {
                float2 xv = *(const float2*)(x + (size_t)(r0 + 8) * D + gcol);
                float2 o;
                o.x = fmaxf(acc[i][j][2], 0.f) + xv.x;
                o.y = fmaxf(acc[i][j][3], 0.f) + xv.y;
                *(float2*)(out + (size_t)(r0 + 8) * D + gcol) = o;
            }
        }
    }
}

// ---------------- causal flash attention (mma.sync, register-resident) ----------------
#define AFM 128
#define AFN 64
#define QLD 72
#define KVLD 72
#define FLASH_SMEM (18432 * 3)

__global__ void __launch_bounds__(256, 2) flash_attn()
{
    extern __shared__ char fsm[];
    bf16* Qs = (bf16*)fsm;
    bf16* K0 = Qs + AFM * QLD;
    bf16* K1 = K0 + AFN * KVLD;
    bf16* V0 = K1 + AFN * KVLD;
    bf16* V1 = V0 + AFN * KVLD;
    bf16* Kst[2] = {K0, K1};
    bf16* Vst[2] = {V0, V1};

    // heavy-first ordering: high-mt blocks launch first
    const int mt = (L / AFM - 1) - blockIdx.x;
    const int hh = blockIdx.y, bb = blockIdx.z;
    const int tid = threadIdx.x;
    const int warp = tid >> 5;
    const int lane = tid & 31;
    const int m0 = mt * AFM;

    const size_t head_off = ((size_t)(bb * H + hh) * L) * DH;
    const bf16* Qg = g_q + head_off;
    const bf16* Kg = g_k + head_off;
    const bf16* Vg = g_v + head_off;

    #pragma unroll
    for (int rep = 0; rep < 4; rep++) {
        int idx = tid + rep * 256;
        int r = idx >> 3, c = (idx & 7) << 3;
        cp16(Qs + r * QLD + c, Qg + (size_t)(m0 + r) * DH + c);
    }
    cp_commit();

    const int ntmax = (m0 + AFM - 1) / AFN;

    #pragma unroll
    for (int st = 0; st < 2; st++) {
        const int n0 = st * AFN;
        #pragma unroll
        for (int rep = 0; rep < 2; rep++) {
            int idx = tid + rep * 256;
            int r = idx >> 3, c = (idx & 7) << 3;
            cp16(Kst[st] + r * KVLD + c, Kg + (size_t)(n0 + r) * DH + c);
            cp16(Vst[st] + r * KVLD + c, Vg + (size_t)(n0 + r) * DH + c);
        }
        cp_commit();
    }

    cp_wait<2>();
    __syncthreads();
    uint32_t qf[4][4];
    {
        const bf16* qa = Qs + (warp * 16 + (lane & 15)) * QLD + ((lane >> 4) << 3);
        #pragma unroll
        for (int kk = 0; kk < 4; kk++)
            ldsm4(qf[kk], qa + kk * 16);
    }

    const int g = lane >> 2;
    const int t4 = lane & 3;
    const int wrow0 = m0 + warp * 16;
    const int r0g = wrow0 + g;
    const int r1g = r0g + 8;

    float o[8][4];
    #pragma unroll
    for (int d = 0; d < 8; d++)
        #pragma unroll
        for (int e = 0; e < 4; e++) o[d][e] = 0.f;
    float m0r = -1e30f, m1r = -1e30f, l0 = 0.f, l1 = 0.f;

    for (int nt = 0; nt <= ntmax; nt++) {
        const int buf = nt & 1;
        const int n0 = nt * AFN;
        if (nt < ntmax) cp_wait<1>(); else cp_wait<0>();
        __syncthreads();

        if (n0 <= wrow0 + 15) {
            bf16* Ks = Kst[buf];
            bf16* Vs = Vst[buf];

            float sc[8][4];
            #pragma unroll
            for (int j = 0; j < 8; j++)
                #pragma unroll
                for (int e = 0; e < 4; e++) sc[j][e] = 0.f;

            #pragma unroll
            for (int kk = 0; kk < 4; kk++) {
                #pragma unroll
                for (int jp = 0; jp < 4; jp++) {
                    uint32_t bfr[4];
                    int row = jp * 16 + (lane & 7) + ((lane >> 4) << 3);
                    int col = kk * 16 + (((lane >> 3) & 1) << 3);
                    ldsm4(bfr, Ks + row * KVLD + col);
                    mma16816(sc[2 * jp],     qf[kk], bfr[0], bfr[1]);
                    mma16816(sc[2 * jp + 1], qf[kk], bfr[2], bfr[3]);
                }
            }

            const bool diag = (n0 + 63 > wrow0);
            float mx0 = m0r, mx1 = m1r;
            #pragma unroll
            for (int j = 0; j < 8; j++) {
                const int c0 = n0 + j * 8 + 2 * t4;
                float s0 = sc[j][0] * 0.125f;
                float s1 = sc[j][1] * 0.125f;
                float s2 = sc[j][2] * 0.125f;
                float s3 = sc[j][3] * 0.125f;
                if (diag) {
                    s0 = (c0     <= r0g) ? s0 : -1e30f;
                    s1 = (c0 + 1 <= r0g) ? s1 : -1e30f;
                    s2 = (c0     <= r1g) ? s2 : -1e30f;
                    s3 = (c0 + 1 <= r1g) ? s3 : -1e30f;
                }
                sc[j][0] = s0; sc[j][1] = s1; sc[j][2] = s2; sc[j][3] = s3;
                mx0 = fmaxf(mx0, fmaxf(s0, s1));
                mx1 = fmaxf(mx1, fmaxf(s2, s3));
            }
            mx0 = fmaxf(mx0, __shfl_xor_sync(0xffffffffu, mx0, 1));
            mx0 = fmaxf(mx0, __shfl_xor_sync(0xffffffffu, mx0, 2));
            mx1 = fmaxf(mx1, __shfl_xor_sync(0xffffffffu, mx1, 1));
            mx1 = fmaxf(mx1, __shfl_xor_sync(0xffffffffu, mx1, 2));

            const float alpha0 = __expf(m0r - mx0);
            const float alpha1 = __expf(m1r - mx1);

            uint32_t pp0[8], pp1[8];
            float sum0 = 0.f, sum1 = 0.f;
            #pragma unroll
            for (int j = 0; j < 8; j++) {
                float p0 = __expf(sc[j][0] - mx0);
                float p1 = __expf(sc[j][1] - mx0);
                float p2 = __expf(sc[j][2] - mx1);
                float p3 = __expf(sc[j][3] - mx1);
                sum0 += p0 + p1;
                sum1 += p2 + p3;
                pp0[j] = pack2bf(p0, p1);
                pp1[j] = pack2bf(p2, p3);
            }
            sum0 += __shfl_xor_sync(0xffffffffu, sum0, 1);
            sum0 += __shfl_xor_sync(0xffffffffu, sum0, 2);
            sum1 += __shfl_xor_sync(0xffffffffu, sum1, 1);
            sum1 += __shfl_xor_sync(0xffffffffu, sum1, 2);

            l0 = l0 * alpha0 + sum0;
            l1 = l1 * alpha1 + sum1;
            m0r = mx0;
            m1r = mx1;

            #pragma unroll
            for (int d = 0; d < 8; d++) {
                o[d][0] *= alpha0; o[d][1] *= alpha0;
                o[d][2] *= alpha1; o[d][3] *= alpha1;
            }

            #pragma unroll
            for (int kt = 0; kt < 4; kt++) {
                uint32_t pa[4] = {pp0[2 * kt], pp1[2 * kt], pp0[2 * kt + 1], pp1[2 * kt + 1]};
                #pragma unroll
                for (int dp = 0; dp < 4; dp++) {
                    uint32_t bfr[4];
                    int row = kt * 16 + (lane & 15);
                    int col = dp * 16 + ((lane >> 4) << 3);
                    ldsm4t(bfr, Vs + row * KVLD + col);
                    mma16816(o[2 * dp],     pa, bfr[0], bfr[1]);
                    mma16816(o[2 * dp + 1], pa, bfr[2], bfr[3]);
                }
            }
        }
        __syncthreads();

        if (nt + 2 <= ntmax) {
            const int nn0 = (nt + 2) * AFN;
            #pragma unroll
            for (int rep = 0; rep < 2; rep++) {
                int idx = tid + rep * 256;
                int r = idx >> 3, c = (idx & 7) << 3;
                cp16(Kst[buf] + r * KVLD + c, Kg + (size_t)(nn0 + r) * DH + c);
                cp16(Vst[buf] + r * KVLD + c, Vg + (size_t)(nn0 + r) * DH + c);
            }
            cp_commit();
        }
    }

    const float rl0 = 1.0f / l0;
    const float rl1 = 1.0f / l1;
    bf16* z0 = g_z + ((size_t)(bb * L + r0g)) * D + hh * DH;
    bf16* z1 = g_z + ((size_t)(bb * L + r1g)) * D + hh * DH;
    #pragma unroll
    for (int d = 0; d < 8; d++) {
        int c = d * 8 + 2 * t4;
        *(uint32_t*)(z0 + c) = pack2bf(o[d][0] * rl0, o[d][1] * rl0);
        *(uint32_t*)(z1 + c) = pack2bf(o[d][2] * rl1, o[d][3] * rl1);
    }
}

// ---------------- layernorm ----------------
__global__ void layernorm_kernel(float* __restrict__ out,
                                 const float* __restrict__ gamma,
                                 const float* __restrict__ beta)
{
    __shared__ float row[D];
    __shared__ float red[8];
    const int r = blockIdx.x;
    const int tid = threadIdx.x;
    float* o = out + (size_t)r * D;

    float s = 0.f;
    for (int c = tid; c < D; c += 256) {
        float v = o[c];
        row[c] = v;
        s += v;
    }
    {
        for (int off = 16; off; off >>= 1) s += __shfl_xor_sync(0xffffffffu, s, off);
        if ((tid & 31) == 0) red[tid >> 5] = s;
        __syncthreads();
        if (tid < 32) {
            float v = (tid < 8) ? red[tid] : 0.f;
            for (int off = 4; off; off >>= 1) v += __shfl_xor_sync(0xffffffffu, v, off);
            if (tid == 0) red[0] = v;
        }
        __syncthreads();
    }
    const float mu = red[0] * (1.0f / D);
    __syncthreads();

    float vs = 0.f;
    for (int c = tid; c < D; c += 256) {
        float d = row[c] - mu;
        vs += d * d;
    }
    {
        for (int off = 16; off; off >>= 1) vs += __shfl_xor_sync(0xffffffffu, vs, off);
        if ((tid & 31) == 0) red[tid >> 5] = vs;
        __syncthreads();
        if (tid < 32) {
            float v = (tid < 8) ? red[tid] : 0.f;
            for (int off = 4; off; off >>= 1) v += __shfl_xor_sync(0xffffffffu, v, off);
            if (tid == 0) red[0] = v;
        }
        __syncthreads();
    }
    const float inv = rsqrtf(red[0] * (1.0f / D) + 1e-12f);

    for (int c = tid; c < D; c += 256)
        o[c] = (row[c] - mu) * inv * gamma[c] + beta[c];
}

// ---------------- launch ----------------
extern "C" void kernel_launch(void* const* d_in, const int* in_sizes, int n_in,
                              void* d_out, int out_size)
{
    const float* x     = (const float*)d_in[0];
    const float* Wq    = (const float*)d_in[1];
    const float* Wk    = (const float*)d_in[2];
    const float* Wv    = (const float*)d_in[3];
    const float* Wo    = (const float*)d_in[4];
    const float* gamma = (const float*)d_in[5];
    const float* beta  = (const float*)d_in[6];
    float* out = (float*)d_out;

    cudaFuncSetAttribute(qkv_gemm, cudaFuncAttributeMaxDynamicSharedMemorySize, GEMM_SMEM);
    cudaFuncSetAttribute(out_gemm, cudaFuncAttributeMaxDynamicSharedMemorySize, GEMM_SMEM);
    cudaFuncSetAttribute(flash_attn, cudaFuncAttributeMaxDynamicSharedMemorySize, FLASH_SMEM);

    convert_x<<<NROWS * D / 4 / 256, 256>>>(x);
    transpose_w<<<dim3(32, 32, 4), dim3(32, 8)>>>(Wq, Wk, Wv, Wo);

    qkv_gemm<<<dim3(3 * D / GBN, NROWS / GBM), 512, GEMM_SMEM>>>();

    flash_attn<<<dim3(L / AFM, H, B), 256, FLASH_SMEM>>>();

    out_gemm<<<dim3(D / GBN, NROWS / GBM), 512, GEMM_SMEM>>>(x, out);

    layernorm_kernel<<<NROWS, 256>>>(out, gamma, beta);
}

// round 12
// speedup vs baseline: 5.7110x; 1.0538x over previous
#include <cuda_runtime.h>
#include <cuda_bf16.h>
#include <math.h>
#include <stdint.h>

#define B 4
#define L 2048
#define D 1024
#define H 16
#define DH 64
#define NROWS (B * L)   // 8192

typedef __nv_bfloat16 bf16;

// ---------------- scratch (no allocations allowed) ----------------
__device__ bf16 g_q[(size_t)B * H * L * DH];
__device__ bf16 g_k[(size_t)B * H * L * DH];
__device__ bf16 g_v[(size_t)B * H * L * DH];
__device__ bf16 g_z[(size_t)NROWS * D];
__device__ bf16 g_xb[(size_t)NROWS * D];
__device__ bf16 g_wqkv[(size_t)3 * D * D];     // [Wq^T;Wk^T;Wv^T] bf16 [3072,1024] (n,k)
__device__ bf16 g_wot[(size_t)D * D];          // Wo^T bf16

// ---------------- helpers ----------------
__device__ __forceinline__ uint2 pack4bf(float4 v) {
    __nv_bfloat162 lo = __float22bfloat162_rn(make_float2(v.x, v.y));
    __nv_bfloat162 hi = __float22bfloat162_rn(make_float2(v.z, v.w));
    uint2 u;
    u.x = *(unsigned int*)&lo;
    u.y = *(unsigned int*)&hi;
    return u;
}
__device__ __forceinline__ uint32_t pack2bf(float a, float b) {
    __nv_bfloat162 h2 = __float22bfloat162_rn(make_float2(a, b));
    return *(unsigned int*)&h2;
}
__device__ __forceinline__ uint32_t smem_u32(const void* p) {
    uint32_t a;
    asm("{ .reg .u64 t; cvta.to.shared.u64 t, %1; cvt.u32.u64 %0, t; }" : "=r"(a) : "l"(p));
    return a;
}
__device__ __forceinline__ void cp16(void* s, const void* g) {
    uint32_t sa = smem_u32(s);
    asm volatile("cp.async.cg.shared.global [%0], [%1], 16;" :: "r"(sa), "l"(g) : "memory");
}
__device__ __forceinline__ void cp_commit() {
    asm volatile("cp.async.commit_group;" ::: "memory");
}
template<int N>
__device__ __forceinline__ void cp_wait() {
    asm volatile("cp.async.wait_group %0;" :: "n"(N) : "memory");
}
__device__ __forceinline__ void ldsm4(uint32_t* r, const void* p) {
    uint32_t a = smem_u32(p);
    asm volatile("ldmatrix.sync.aligned.m8n8.x4.shared.b16 {%0,%1,%2,%3}, [%4];"
                 : "=r"(r[0]), "=r"(r[1]), "=r"(r[2]), "=r"(r[3]) : "r"(a));
}
__device__ __forceinline__ void ldsm4t(uint32_t* r, const void* p) {
    uint32_t a = smem_u32(p);
    asm volatile("ldmatrix.sync.aligned.m8n8.x4.trans.shared.b16 {%0,%1,%2,%3}, [%4];"
                 : "=r"(r[0]), "=r"(r[1]), "=r"(r[2]), "=r"(r[3]) : "r"(a));
}
__device__ __forceinline__ void mma16816(float* c, const uint32_t* a, uint32_t b0, uint32_t b1) {
    asm volatile(
        "mma.sync.aligned.m16n8k16.row.col.f32.bf16.bf16.f32 "
        "{%0,%1,%2,%3}, {%4,%5,%6,%7}, {%8,%9}, {%0,%1,%2,%3};"
        : "+f"(c[0]), "+f"(c[1]), "+f"(c[2]), "+f"(c[3])
        : "r"(a[0]), "r"(a[1]), "r"(a[2]), "r"(a[3]), "r"(b0), "r"(b1));
}

// ---------------- one-shot converts ----------------
__global__ void convert_x(const float* __restrict__ x) {
    size_t i = (size_t)(blockIdx.x * blockDim.x + threadIdx.x) * 4;
    float4 v = *(const float4*)(x + i);
    *(uint2*)(g_xb + i) = pack4bf(v);
}

__global__ void transpose_w(const float* __restrict__ Wq, const float* __restrict__ Wk,
                            const float* __restrict__ Wv, const float* __restrict__ Wo) {
    __shared__ float tile[32][33];
    const int z = blockIdx.z;
    const float* W = (z == 0) ? Wq : (z == 1) ? Wk : (z == 2) ? Wv : Wo;
    bf16* T = (z < 3) ? (g_wqkv + (size_t)z * D * D) : g_wot;
    int x0 = blockIdx.x * 32, y0 = blockIdx.y * 32;
    int tx = threadIdx.x, ty = threadIdx.y;
    #pragma unroll
    for (int i = 0; i < 4; i++)
        tile[ty + i * 8][tx] = W[(size_t)(y0 + ty + i * 8) * D + x0 + tx];
    __syncthreads();
    #pragma unroll
    for (int i = 0; i < 4; i++)
        T[(size_t)(x0 + ty + i * 8) * D + y0 + tx] = __float2bfloat16(tile[tx][ty + i * 8]);
}

// ---------------- mma.sync GEMM: 128x256 tile, BK=64, 2-stage, 512 threads ----------------
#define GBM 128
#define GBN 256
#define GBK 64
#define GALD 72
#define GA_STAGE (GBM * GALD)
#define GB_STAGE (GBN * GALD)
#define GEMM_SMEM ((GA_STAGE + GB_STAGE) * 2 * 2)   // 110592 B

// warp grid 2(M) x 8(N); acc[i 0..3][j 0..3][4]
__device__ __forceinline__ void gemm_mainloop(
    const bf16* __restrict__ Ag, const bf16* __restrict__ Bt,
    bf16* As, bf16* Bs, int row0, int col0, float acc[4][4][4])
{
    const int tid = threadIdx.x;
    const int warp = tid >> 5;
    const int lane = tid & 31;
    const int wm = warp >> 3;
    const int wn = warp & 7;

    #pragma unroll
    for (int i = 0; i < 4; i++)
        #pragma unroll
        for (int j = 0; j < 4; j++)
            #pragma unroll
            for (int e = 0; e < 4; e++) acc[i][j][e] = 0.f;

    const int NT = D / GBK;   // 16

    #pragma unroll
    for (int s = 0; s < 2; s++) {
        const int k0 = s * GBK;
        bf16* A = As + s * GA_STAGE;
        bf16* Bst = Bs + s * GB_STAGE;
        #pragma unroll
        for (int rep = 0; rep < 2; rep++) {
            int idx = tid + rep * 512;
            int r = idx >> 3, c = idx & 7;
            cp16(A + r * GALD + c * 8, Ag + (size_t)(row0 + r) * D + k0 + c * 8);
        }
        #pragma unroll
        for (int rep = 0; rep < 4; rep++) {
            int idx = tid + rep * 512;
            int r = idx >> 3, c = idx & 7;
            cp16(Bst + r * GALD + c * 8, Bt + (size_t)(col0 + r) * D + k0 + c * 8);
        }
        cp_commit();
    }

    for (int t = 0; t < NT; t++) {
        if (t + 2 < NT + 1) cp_wait<1>();
        if (t + 1 == NT) cp_wait<0>();
        __syncthreads();
        const int s = t & 1;
        const bf16* A = As + s * GA_STAGE;
        const bf16* Bst = Bs + s * GB_STAGE;

        #pragma unroll
        for (int ks = 0; ks < 4; ks++) {
            uint32_t af[4][4];
            #pragma unroll
            for (int i = 0; i < 4; i++)
                ldsm4(af[i], A + (wm * 64 + i * 16 + (lane & 15)) * GALD
                             + ks * 16 + ((lane >> 4) << 3));
            #pragma unroll
            for (int jp = 0; jp < 2; jp++) {
                uint32_t bfr[4];
                ldsm4(bfr, Bst + (wn * 32 + jp * 16 + (lane & 7) + ((lane >> 4) << 3)) * GALD
                           + ks * 16 + (((lane >> 3) & 1) << 3));
                #pragma unroll
                for (int i = 0; i < 4; i++) {
                    mma16816(acc[i][2 * jp],     af[i], bfr[0], bfr[1]);
                    mma16816(acc[i][2 * jp + 1], af[i], bfr[2], bfr[3]);
                }
            }
        }
        __syncthreads();

        if (t + 2 < NT) {
            const int k0 = (t + 2) * GBK;
            bf16* An = As + s * GA_STAGE;
            bf16* Bn = Bs + s * GB_STAGE;
            #pragma unroll
            for (int rep = 0; rep < 2; rep++) {
                int idx = tid + rep * 512;
                int r = idx >> 3, c = idx & 7;
                cp16(An + r * GALD + c * 8, Ag + (size_t)(row0 + r) * D + k0 + c * 8);
            }
            #pragma unroll
            for (int rep = 0; rep < 4; rep++) {
                int idx = tid + rep * 512;
                int r = idx >> 3, c = idx & 7;
                cp16(Bn + r * GALD + c * 8, Bt + (size_t)(col0 + r) * D + k0 + c * 8);
            }
            cp_commit();
        }
    }
}

// fused QKV: grid (12, 64), 512 threads
__global__ void __launch_bounds__(512, 1) qkv_gemm()
{
    extern __shared__ char smem[];
    bf16* As = (bf16*)smem;
    bf16* Bs = As + 2 * GA_STAGE;

    const int row0 = blockIdx.y * GBM;
    const int col0 = blockIdx.x * GBN;

    float acc[4][4][4];
    gemm_mainloop(g_xb, g_wqkv, As, Bs, row0, col0, acc);

    const int warp = threadIdx.x >> 5;
    const int lane = threadIdx.x & 31;
    const int wm = warp >> 3, wn = warp & 7;
    const int g = lane >> 2, t4 = lane & 3;

    #pragma unroll
    for (int i = 0; i < 4; i++) {
        const int r0 = row0 + wm * 64 + i * 16 + g;
        const int b = r0 >> 11, l = r0 & 2047;
        #pragma unroll
        for (int j = 0; j < 4; j++) {
            int gcol = col0 + wn * 32 + j * 8 + 2 * t4;
            int sel = gcol >> 10;
            int hc = gcol & 1023;
            int h = hc >> 6, d = hc & 63;
            bf16* Out = (sel == 0) ? g_q : (sel == 1) ? g_k : g_v;
            size_t base = ((size_t)(b * H + h) * L + l) * DH + d;
            *(uint32_t*)(Out + base)          = pack2bf(acc[i][j][0], acc[i][j][1]);
            *(uint32_t*)(Out + base + 8 * DH) = pack2bf(acc[i][j][2], acc[i][j][3]);
        }
    }
}

// out projection: grid (4, 64), 512 threads; fused relu + residual
__global__ void __launch_bounds__(512, 1) out_gemm(const float* __restrict__ x,
                                                   float* __restrict__ out)
{
    extern __shared__ char smem[];
    bf16* As = (bf16*)smem;
    bf16* Bs = As + 2 * GA_STAGE;

    const int row0 = blockIdx.y * GBM;
    const int col0 = blockIdx.x * GBN;

    float acc[4][4][4];
    gemm_mainloop(g_z, g_wot, As, Bs, row0, col0, acc);

    const int warp = threadIdx.x >> 5;
    const int lane = threadIdx.x & 31;
    const int wm = warp >> 3, wn = warp & 7;
    const int g = lane >> 2, t4 = lane & 3;

    #pragma unroll
    for (int i = 0; i < 4; i++) {
        const int r0 = row0 + wm * 64 + i * 16 + g;
        #pragma unroll
        for (int j = 0; j < 4; j++) {
            int gcol = col0 + wn * 32 + j * 8 + 2 * t4;
            {
                float2 xv = *(const float2*)(x + (size_t)r0 * D + gcol);
                float2 o;
                o.x = fmaxf(acc[i][j][0], 0.f) + xv.x;
                o.y = fmaxf(acc[i][j][1], 0.f) + xv.y;
                *(float2*)(out + (size_t)r0 * D + gcol) = o;
            }
            {
                float2 xv = *(const float2*)(x + (size_t)(r0 + 8) * D + gcol);
                float2 o;
                o.x = fmaxf(acc[i][j][2], 0.f) + xv.x;
                o.y = fmaxf(acc[i][j][3], 0.f) + xv.y;
                *(float2*)(out + (size_t)(r0 + 8) * D + gcol) = o;
            }
        }
    }
}

// ---------------- causal flash attention: 64-row CTAs, 4 warps, 4 CTAs/SM ----------------
#define AFM 64
#define AFN 64
#define QLD 72
#define KVLD 72
#define FLASH_SMEM (9216 * 5)   // 46080

__global__ void __launch_bounds__(128, 4) flash_attn()
{
    extern __shared__ char fsm[];
    bf16* Qs = (bf16*)fsm;
    bf16* K0 = Qs + AFM * QLD;
    bf16* K1 = K0 + AFN * KVLD;
    bf16* V0 = K1 + AFN * KVLD;
    bf16* V1 = V0 + AFN * KVLD;
    bf16* Kst[2] = {K0, K1};
    bf16* Vst[2] = {V0, V1};

    // heavy-first ordering
    const int mt = (L / AFM - 1) - blockIdx.x;
    const int hh = blockIdx.y, bb = blockIdx.z;
    const int tid = threadIdx.x;
    const int warp = tid >> 5;
    const int lane = tid & 31;
    const int m0 = mt * AFM;

    const size_t head_off = ((size_t)(bb * H + hh) * L) * DH;
    const bf16* Qg = g_q + head_off;
    const bf16* Kg = g_k + head_off;
    const bf16* Vg = g_v + head_off;

    #pragma unroll
    for (int rep = 0; rep < 4; rep++) {
        int idx = tid + rep * 128;
        int r = idx >> 3, c = (idx & 7) << 3;
        cp16(Qs + r * QLD + c, Qg + (size_t)(m0 + r) * DH + c);
    }
    cp_commit();

    const int ntmax = mt;

    #pragma unroll
    for (int st = 0; st < 2; st++) {
        const int n0 = st * AFN;
        #pragma unroll
        for (int rep = 0; rep < 4; rep++) {
            int idx = tid + rep * 128;
            int r = idx >> 3, c = (idx & 7) << 3;
            cp16(Kst[st] + r * KVLD + c, Kg + (size_t)(n0 + r) * DH + c);
            cp16(Vst[st] + r * KVLD + c, Vg + (size_t)(n0 + r) * DH + c);
        }
        cp_commit();
    }

    cp_wait<2>();
    __syncthreads();
    uint32_t qf[4][4];
    {
        const bf16* qa = Qs + (warp * 16 + (lane & 15)) * QLD + ((lane >> 4) << 3);
        #pragma unroll
        for (int kk = 0; kk < 4; kk++)
            ldsm4(qf[kk], qa + kk * 16);
    }

    const int g = lane >> 2;
    const int t4 = lane & 3;
    const int wrow0 = m0 + warp * 16;
    const int r0g = wrow0 + g;
    const int r1g = r0g + 8;

    float o[8][4];
    #pragma unroll
    for (int d = 0; d < 8; d++)
        #pragma unroll
        for (int e = 0; e < 4; e++) o[d][e] = 0.f;
    float m0r = -1e30f, m1r = -1e30f, l0 = 0.f, l1 = 0.f;

    for (int nt = 0; nt <= ntmax; nt++) {
        const int buf = nt & 1;
        const int n0 = nt * AFN;
        if (nt < ntmax) cp_wait<1>(); else cp_wait<0>();
        __syncthreads();

        {
            bf16* Ks = Kst[buf];
            bf16* Vs = Vst[buf];

            float sc[8][4];
            #pragma unroll
            for (int j = 0; j < 8; j++)
                #pragma unroll
                for (int e = 0; e < 4; e++) sc[j][e] = 0.f;

            #pragma unroll
            for (int kk = 0; kk < 4; kk++) {
                #pragma unroll
                for (int jp = 0; jp < 4; jp++) {
                    uint32_t bfr[4];
                    int row = jp * 16 + (lane & 7) + ((lane >> 4) << 3);
                    int col = kk * 16 + (((lane >> 3) & 1) << 3);
                    ldsm4(bfr, Ks + row * KVLD + col);
                    mma16816(sc[2 * jp],     qf[kk], bfr[0], bfr[1]);
                    mma16816(sc[2 * jp + 1], qf[kk], bfr[2], bfr[3]);
                }
            }

            const bool diag = (n0 + 63 > wrow0);
            float mx0 = m0r, mx1 = m1r;
            #pragma unroll
            for (int j = 0; j < 8; j++) {
                const int c0 = n0 + j * 8 + 2 * t4;
                float s0 = sc[j][0] * 0.125f;
                float s1 = sc[j][1] * 0.125f;
                float s2 = sc[j][2] * 0.125f;
                float s3 = sc[j][3] * 0.125f;
                if (diag) {
                    s0 = (c0     <= r0g) ? s0 : -1e30f;
                    s1 = (c0 + 1 <= r0g) ? s1 : -1e30f;
                    s2 = (c0     <= r1g) ? s2 : -1e30f;
                    s3 = (c0 + 1 <= r1g) ? s3 : -1e30f;
                }
                sc[j][0] = s0; sc[j][1] = s1; sc[j][2] = s2; sc[j][3] = s3;
                mx0 = fmaxf(mx0, fmaxf(s0, s1));
                mx1 = fmaxf(mx1, fmaxf(s2, s3));
            }
            mx0 = fmaxf(mx0, __shfl_xor_sync(0xffffffffu, mx0, 1));
            mx0 = fmaxf(mx0, __shfl_xor_sync(0xffffffffu, mx0, 2));
            mx1 = fmaxf(mx1, __shfl_xor_sync(0xffffffffu, mx1, 1));
            mx1 = fmaxf(mx1, __shfl_xor_sync(0xffffffffu, mx1, 2));

            const float alpha0 = __expf(m0r - mx0);
            const float alpha1 = __expf(m1r - mx1);

            uint32_t pp0[8], pp1[8];
            float sum0 = 0.f, sum1 = 0.f;
            #pragma unroll
            for (int j = 0; j < 8; j++) {
                float p0 = __expf(sc[j][0] - mx0);
                float p1 = __expf(sc[j][1] - mx0);
                float p2 = __expf(sc[j][2] - mx1);
                float p3 = __expf(sc[j][3] - mx1);
                sum0 += p0 + p1;
                sum1 += p2 + p3;
                pp0[j] = pack2bf(p0, p1);
                pp1[j] = pack2bf(p2, p3);
            }
            sum0 += __shfl_xor_sync(0xffffffffu, sum0, 1);
            sum0 += __shfl_xor_sync(0xffffffffu, sum0, 2);
            sum1 += __shfl_xor_sync(0xffffffffu, sum1, 1);
            sum1 += __shfl_xor_sync(0xffffffffu, sum1, 2);

            l0 = l0 * alpha0 + sum0;
            l1 = l1 * alpha1 + sum1;
            m0r = mx0;
            m1r = mx1;

            #pragma unroll
            for (int d = 0; d < 8; d++) {
                o[d][0] *= alpha0; o[d][1] *= alpha0;
                o[d][2] *= alpha1; o[d][3] *= alpha1;
            }

            #pragma unroll
            for (int kt = 0; kt < 4; kt++) {
                uint32_t pa[4] = {pp0[2 * kt], pp1[2 * kt], pp0[2 * kt + 1], pp1[2 * kt + 1]};
                #pragma unroll
                for (int dp = 0; dp < 4; dp++) {
                    uint32_t bfr[4];
                    int row = kt * 16 + (lane & 15);
                    int col = dp * 16 + ((lane >> 4) << 3);
                    ldsm4t(bfr, Vs + row * KVLD + col);
                    mma16816(o[2 * dp],     pa, bfr[0], bfr[1]);
                    mma16816(o[2 * dp + 1], pa, bfr[2], bfr[3]);
                }
            }
        }
        __syncthreads();

        if (nt + 2 <= ntmax) {
            const int nn0 = (nt + 2) * AFN;
            #pragma unroll
            for (int rep = 0; rep < 4; rep++) {
                int idx = tid + rep * 128;
                int r = idx >> 3, c = (idx & 7) << 3;
                cp16(Kst[buf] + r * KVLD + c, Kg + (size_t)(nn0 + r) * DH + c);
                cp16(Vst[buf] + r * KVLD + c, Vg + (size_t)(nn0 + r) * DH + c);
            }
            cp_commit();
        }
    }

    const float rl0 = 1.0f / l0;
    const float rl1 = 1.0f / l1;
    bf16* z0 = g_z + ((size_t)(bb * L + r0g)) * D + hh * DH;
    bf16* z1 = g_z + ((size_t)(bb * L + r1g)) * D + hh * DH;
    #pragma unroll
    for (int d = 0; d < 8; d++) {
        int c = d * 8 + 2 * t4;
        *(uint32_t*)(z0 + c) = pack2bf(o[d][0] * rl0, o[d][1] * rl0);
        *(uint32_t*)(z1 + c) = pack2bf(o[d][2] * rl1, o[d][3] * rl1);
    }
}

// ---------------- layernorm ----------------
__global__ void layernorm_kernel(float* __restrict__ out,
                                 const float* __restrict__ gamma,
                                 const float* __restrict__ beta)
{
    __shared__ float row[D];
    __shared__ float red[8];
    const int r = blockIdx.x;
    const int tid = threadIdx.x;
    float* o = out + (size_t)r * D;

    float s = 0.f;
    for (int c = tid; c < D; c += 256) {
        float v = o[c];
        row[c] = v;
        s += v;
    }
    {
        for (int off = 16; off; off >>= 1) s += __shfl_xor_sync(0xffffffffu, s, off);
        if ((tid & 31) == 0) red[tid >> 5] = s;
        __syncthreads();
        if (tid < 32) {
            float v = (tid < 8) ? red[tid] : 0.f;
            for (int off = 4; off; off >>= 1) v += __shfl_xor_sync(0xffffffffu, v, off);
            if (tid == 0) red[0] = v;
        }
        __syncthreads();
    }
    const float mu = red[0] * (1.0f / D);
    __syncthreads();

    float vs = 0.f;
    for (int c = tid; c < D; c += 256) {
        float d = row[c] - mu;
        vs += d * d;
    }
    {
        for (int off = 16; off; off >>= 1) vs += __shfl_xor_sync(0xffffffffu, vs, off);
        if ((tid & 31) == 0) red[tid >> 5] = vs;
        __syncthreads();
        if (tid < 32) {
            float v = (tid < 8) ? red[tid] : 0.f;
            for (int off = 4; off; off >>= 1) v += __shfl_xor_sync(0xffffffffu, v, off);
            if (tid == 0) red[0] = v;
        }
        __syncthreads();
    }
    const float inv = rsqrtf(red[0] * (1.0f / D) + 1e-12f);

    for (int c = tid; c < D; c += 256)
        o[c] = (row[c] - mu) * inv * gamma[c] + beta[c];
}

// ---------------- launch ----------------
extern "C" void kernel_launch(void* const* d_in, const int* in_sizes, int n_in,
                              void* d_out, int out_size)
{
    const float* x     = (const float*)d_in[0];
    const float* Wq    = (const float*)d_in[1];
    const float* Wk    = (const float*)d_in[2];
    const float* Wv    = (const float*)d_in[3];
    const float* Wo    = (const float*)d_in[4];
    const float* gamma = (const float*)d_in[5];
    const float* beta  = (const float*)d_in[6];
    float* out = (float*)d_out;

    cudaFuncSetAttribute(qkv_gemm, cudaFuncAttributeMaxDynamicSharedMemorySize, GEMM_SMEM);
    cudaFuncSetAttribute(out_gemm, cudaFuncAttributeMaxDynamicSharedMemorySize, GEMM_SMEM);
    cudaFuncSetAttribute(flash_attn, cudaFuncAttributeMaxDynamicSharedMemorySize, FLASH_SMEM);

    convert_x<<<NROWS * D / 4 / 256, 256>>>(x);
    transpose_w<<<dim3(32, 32, 4), dim3(32, 8)>>>(Wq, Wk, Wv, Wo);

    qkv_gemm<<<dim3(3 * D / GBN, NROWS / GBM), 512, GEMM_SMEM>>>();

    flash_attn<<<dim3(L / AFM, H, B), 128, FLASH_SMEM>>>();

    out_gemm<<<dim3(D / GBN, NROWS / GBM), 512, GEMM_SMEM>>>(x, out);

    layernorm_kernel<<<NROWS, 256>>>(out, gamma, beta);
}